// round 5
// baseline (speedup 1.0000x reference)
#include <cuda_runtime.h>

#define NAB 256
#define NAGN 16384
#define NTOT 16640
#define DDIM 128
#define GSZ 2048

typedef unsigned long long ull;

// ---------------- scratch (device globals; no allocation) ----------------
__device__ float g_h[NTOT * DDIM];
__device__ float g_y[NTOT * DDIM];
__device__ float g_z[NTOT * DDIM];
__device__ float g_als[NTOT];
__device__ float g_ald[NTOT];
__device__ float g_zsum[NAB];
__device__ float g_sum[2 * DDIM];
__device__ float g_ssq[2 * DDIM];
__device__ float g_scA[2 * DDIM];
__device__ float g_shA[2 * DDIM];

__device__ __forceinline__ float lrelu(float e) { return e > 0.f ? e : 0.2f * e; }

// ---- packed f32x2 helpers (Blackwell FFMA2) ----
__device__ __forceinline__ ull dup2(float s) {
    ull d; unsigned u = __float_as_uint(s);
    asm("mov.b64 %0, {%1, %1};" : "=l"(d) : "r"(u));
    return d;
}
__device__ __forceinline__ void ffma2(ull& acc, ull a, ull b) {
    asm("fma.rn.f32x2 %0, %1, %2, %0;" : "+l"(acc) : "l"(a), "l"(b));
}
__device__ __forceinline__ void unpk(float& lo, float& hi, ull v) {
    unsigned a, b;
    asm("mov.b64 {%0, %1}, %2;" : "=r"(a), "=r"(b) : "l"(v));
    lo = __uint_as_float(a); hi = __uint_as_float(b);
}

// ---------------- GEMM: H = X @ W, plus al_src/al_dst row dots ----------------
// 260 blocks x 256 thr, 64 rows/block. Thread tile 4 rows x 8 cols (FFMA2-paired).
__global__ void __launch_bounds__(256, 2)
k_gemm(const float* __restrict__ X0, const float* __restrict__ X1,
       const float* __restrict__ W,
       const float* __restrict__ asrc, const float* __restrict__ adst,
       float* __restrict__ H, float* __restrict__ ALS, float* __restrict__ ALD,
       float* __restrict__ yz) {
    extern __shared__ float sm[];
    float* Ws = sm;                  // 128*128
    float* Xs = sm + 16384;          // 64*128
    float* as_sh = sm + 24576;       // 128
    float* ad_sh = sm + 24704;       // 128
    const int t = threadIdx.x;
    const int row0 = blockIdx.x * 64;

    // zero AB region of aggregation target + zsum (blocks 0..3)
    if (row0 < NAB) {
        float4* z4 = reinterpret_cast<float4*>(yz) + row0 * 32;
#pragma unroll
        for (int i = 0; i < 8; i++) z4[t + 256 * i] = make_float4(0.f, 0.f, 0.f, 0.f);
        if (blockIdx.x == 0 && t < 128) { g_zsum[t] = 0.f; g_zsum[t + 128] = 0.f; }
    }

    const float* X = (row0 < NAB) ? (X0 + (size_t)row0 * DDIM)
                                  : (X1 + (size_t)(row0 - NAB) * DDIM);

    const float4* W4 = reinterpret_cast<const float4*>(W);
    float4* Ws4s = reinterpret_cast<float4*>(Ws);
#pragma unroll
    for (int i = 0; i < 16; i++) Ws4s[t + 256 * i] = W4[t + 256 * i];
    const float4* Xg4 = reinterpret_cast<const float4*>(X);
    float4* Xs4s = reinterpret_cast<float4*>(Xs);
#pragma unroll
    for (int i = 0; i < 8; i++) Xs4s[t + 256 * i] = Xg4[t + 256 * i];
    if (t < 128) { as_sh[t] = asrc[t]; ad_sh[t] = adst[t]; }
    __syncthreads();

    const int cg = t & 15;      // col group: cols 8*cg .. 8*cg+7
    const int rg = t >> 4;      // row group: rows 4*rg .. 4*rg+3
    ull acc[4][4];              // [row][col-pair]
#pragma unroll
    for (int r = 0; r < 4; r++)
#pragma unroll
        for (int c = 0; c < 4; c++) acc[r][c] = 0ull;

    const ulonglong2* Wsu = reinterpret_cast<const ulonglong2*>(Ws);
    const float4* Xs4 = reinterpret_cast<const float4*>(Xs);

#pragma unroll 2
    for (int k0 = 0; k0 < DDIM; k0 += 4) {
        ulonglong2 wa[4], wb[4];
#pragma unroll
        for (int kk = 0; kk < 4; kk++) {
            wa[kk] = Wsu[(k0 + kk) * 32 + 2 * cg];
            wb[kk] = Wsu[(k0 + kk) * 32 + 2 * cg + 1];
        }
#pragma unroll
        for (int r = 0; r < 4; r++) {
            float4 xr = Xs4[(rg * 4 + r) * 32 + (k0 >> 2)];
            ull xd;
            xd = dup2(xr.x);
            ffma2(acc[r][0], xd, wa[0].x); ffma2(acc[r][1], xd, wa[0].y);
            ffma2(acc[r][2], xd, wb[0].x); ffma2(acc[r][3], xd, wb[0].y);
            xd = dup2(xr.y);
            ffma2(acc[r][0], xd, wa[1].x); ffma2(acc[r][1], xd, wa[1].y);
            ffma2(acc[r][2], xd, wb[1].x); ffma2(acc[r][3], xd, wb[1].y);
            xd = dup2(xr.z);
            ffma2(acc[r][0], xd, wa[2].x); ffma2(acc[r][1], xd, wa[2].y);
            ffma2(acc[r][2], xd, wb[2].x); ffma2(acc[r][3], xd, wb[2].y);
            xd = dup2(xr.w);
            ffma2(acc[r][0], xd, wa[3].x); ffma2(acc[r][1], xd, wa[3].y);
            ffma2(acc[r][2], xd, wb[3].x); ffma2(acc[r][3], xd, wb[3].y);
        }
    }

    float4* H4 = reinterpret_cast<float4*>(H + (size_t)row0 * DDIM);
    float4 asa = reinterpret_cast<const float4*>(as_sh)[2 * cg];
    float4 asb = reinterpret_cast<const float4*>(as_sh)[2 * cg + 1];
    float4 ada = reinterpret_cast<const float4*>(ad_sh)[2 * cg];
    float4 adb = reinterpret_cast<const float4*>(ad_sh)[2 * cg + 1];
#pragma unroll
    for (int r = 0; r < 4; r++) {
        const int lrow = rg * 4 + r;
        float4 v1, v2;
        unpk(v1.x, v1.y, acc[r][0]);
        unpk(v1.z, v1.w, acc[r][1]);
        unpk(v2.x, v2.y, acc[r][2]);
        unpk(v2.z, v2.w, acc[r][3]);
        H4[lrow * 32 + 2 * cg] = v1;
        H4[lrow * 32 + 2 * cg + 1] = v2;
        float ps = v1.x * asa.x + v1.y * asa.y + v1.z * asa.z + v1.w * asa.w
                 + v2.x * asb.x + v2.y * asb.y + v2.z * asb.z + v2.w * asb.w;
        float pd = v1.x * ada.x + v1.y * ada.y + v1.z * ada.z + v1.w * ada.w
                 + v2.x * adb.x + v2.y * adb.y + v2.z * adb.z + v2.w * adb.w;
#pragma unroll
        for (int off = 8; off; off >>= 1) {
            ps += __shfl_xor_sync(0xffffffffu, ps, off);
            pd += __shfl_xor_sync(0xffffffffu, pd, off);
        }
        if (cg == 0) {
            ALS[row0 + lrow] = ps;
            ALD[row0 + lrow] = pd;
        }
    }
}

// ---------------- fused aggregation + softmax (no max-shift) ----------------
// blocks 0..255: AB dsts (batch, 256-src chunk, dst-octet), partial sums + z via atomics
// blocks 256..511: AG dsts, 64 dsts/block (8 per warp), fused softmax + weighted sum
__global__ void __launch_bounds__(256, 2)
k_agg(const float* __restrict__ h, const float* __restrict__ als,
      const float* __restrict__ ald, const float* __restrict__ bias,
      float* __restrict__ y, int do_relu) {
    __shared__ __align__(16) float sbig[8192];      // AB: w[256][8] + staging | AG: h_ab 32x128
    __shared__ __align__(16) float swT[8][32][8];   // AG: per-warp src weights (8 dsts)
    __shared__ float ssmall[16];
    __shared__ float als_sh[32];
    const int t = threadIdx.x;

    if (blockIdx.x < 256) {
        // -------- AB dsts --------
        const int blk = blockIdx.x;
        const int b = blk >> 5, q = (blk >> 2) & 7, dq = blk & 3;
        const int base = NAB + b * GSZ + q * 256;
        const int d0 = b * 32 + dq * 8;
        float* ald_sh = ssmall;
        float* szs = ssmall + 8;
        if (t < 8) { ald_sh[t] = ald[d0 + t]; szs[t] = 0.f; }
        __syncthreads();
        {
            const int dme = t & 7;
            const float aldme = ald_sh[dme];
            float zloc = 0.f;
#pragma unroll
            for (int i = 0; i < 8; i++) {
                int idx = t + 256 * i;
                int j = idx >> 3;
                float e = __expf(lrelu(als[base + j] + aldme));
                sbig[idx] = e;
                zloc += e;
            }
            atomicAdd(&szs[dme], zloc);
        }
        __syncthreads();
        if (t < 8) atomicAdd(&g_zsum[d0 + t], szs[t]);

        const int c4 = t & 31, rs = t >> 5;
        ull acc2[4][4];
#pragma unroll
        for (int dp = 0; dp < 4; dp++)
#pragma unroll
            for (int c = 0; c < 4; c++) acc2[dp][c] = 0ull;

        const float4* h4 = reinterpret_cast<const float4*>(h) + (size_t)base * 32 + c4;
        const ull* w8 = reinterpret_cast<const ull*>(sbig);
#pragma unroll 4
        for (int jj = 0; jj < 32; jj++) {
            const int j = rs * 32 + jj;
            float4 hv = h4[(size_t)j * 32];
            ull hd0 = dup2(hv.x), hd1 = dup2(hv.y), hd2 = dup2(hv.z), hd3 = dup2(hv.w);
#pragma unroll
            for (int dp = 0; dp < 4; dp++) {
                ull a = w8[j * 4 + dp];
                ffma2(acc2[dp][0], a, hd0); ffma2(acc2[dp][1], a, hd1);
                ffma2(acc2[dp][2], a, hd2); ffma2(acc2[dp][3], a, hd3);
            }
        }
        __syncthreads();
        float4* st4 = reinterpret_cast<float4*>(sbig) + rs * 256;
#pragma unroll
        for (int dp = 0; dp < 4; dp++) {
            float4 ve, vo;
            unpk(ve.x, vo.x, acc2[dp][0]);
            unpk(ve.y, vo.y, acc2[dp][1]);
            unpk(ve.z, vo.z, acc2[dp][2]);
            unpk(ve.w, vo.w, acc2[dp][3]);
            st4[(2 * dp) * 32 + c4] = ve;
            st4[(2 * dp + 1) * 32 + c4] = vo;
        }
        __syncthreads();
        float s0 = 0.f, s1 = 0.f, s2 = 0.f, s3 = 0.f;
#pragma unroll
        for (int rr = 0; rr < 8; rr++) {
            float4 v = reinterpret_cast<const float4*>(sbig)[rr * 256 + t];
            s0 += v.x; s1 += v.y; s2 += v.z; s3 += v.w;
        }
        const int d = t >> 5, c = (t & 31) * 4;
        float* yo = y + (size_t)(d0 + d) * DDIM + c;
        atomicAdd(yo + 0, s0); atomicAdd(yo + 1, s1);
        atomicAdd(yo + 2, s2); atomicAdd(yo + 3, s3);
    } else {
        // -------- AG dsts: warp handles 8 dsts; 32-row h_ab tile in smem --------
        const int ablk = blockIdx.x - 256;
        const int b = ablk >> 5, chunk = ablk & 31;
        {
            const float4* hsrc = reinterpret_cast<const float4*>(h + (size_t)b * 32 * DDIM);
            float4* hd = reinterpret_cast<float4*>(sbig);
#pragma unroll
            for (int i = 0; i < 4; i++) hd[t + 256 * i] = hsrc[t + 256 * i];
        }
        if (t < 32) als_sh[t] = als[b * 32 + t];
        __syncthreads();
        const int w = t >> 5, l = t & 31;
        const int j0 = NAB + b * GSZ + chunk * 64 + w * 8;

        float wv[8], inv[8], wself[8];
#pragma unroll
        for (int d = 0; d < 8; d++) {
            float aldv = ald[j0 + d];
            wv[d] = __expf(lrelu(als_sh[l] + aldv));
            wself[d] = __expf(lrelu(als[j0 + d] + aldv));
            float s = wv[d];
#pragma unroll
            for (int off = 16; off; off >>= 1) s += __shfl_xor_sync(0xffffffffu, s, off);
            inv[d] = 1.f / (s + wself[d] + 1e-16f);
        }
        {
            float4* swp = reinterpret_cast<float4*>(&swT[w][l][0]);
            swp[0] = make_float4(wv[0], wv[1], wv[2], wv[3]);
            swp[1] = make_float4(wv[4], wv[5], wv[6], wv[7]);
        }
        __syncwarp();

        ull acc[4][4];   // [dst-pair][col]
#pragma unroll
        for (int dp = 0; dp < 4; dp++)
#pragma unroll
            for (int c = 0; c < 4; c++) acc[dp][c] = 0ull;

        const float4* hab4 = reinterpret_cast<const float4*>(sbig);
        const ulonglong2* swu = reinterpret_cast<const ulonglong2*>(&swT[w][0][0]);
#pragma unroll 4
        for (int l2 = 0; l2 < 32; l2++) {
            ulonglong2 u0 = swu[l2 * 2];
            ulonglong2 u1 = swu[l2 * 2 + 1];
            float4 hv = hab4[l2 * 32 + l];
            ull hd;
            hd = dup2(hv.x);
            ffma2(acc[0][0], u0.x, hd); ffma2(acc[1][0], u0.y, hd);
            ffma2(acc[2][0], u1.x, hd); ffma2(acc[3][0], u1.y, hd);
            hd = dup2(hv.y);
            ffma2(acc[0][1], u0.x, hd); ffma2(acc[1][1], u0.y, hd);
            ffma2(acc[2][1], u1.x, hd); ffma2(acc[3][1], u1.y, hd);
            hd = dup2(hv.z);
            ffma2(acc[0][2], u0.x, hd); ffma2(acc[1][2], u0.y, hd);
            ffma2(acc[2][2], u1.x, hd); ffma2(acc[3][2], u1.y, hd);
            hd = dup2(hv.w);
            ffma2(acc[0][3], u0.x, hd); ffma2(acc[1][3], u0.y, hd);
            ffma2(acc[2][3], u1.x, hd); ffma2(acc[3][3], u1.y, hd);
        }

        float4 b4 = reinterpret_cast<const float4*>(bias)[l];
#pragma unroll
        for (int dp = 0; dp < 4; dp++) {
            float sd0[4], sd1[4];
#pragma unroll
            for (int c = 0; c < 4; c++) unpk(sd0[c], sd1[c], acc[dp][c]);
            const int da = 2 * dp, db = 2 * dp + 1;
            float4 ha = reinterpret_cast<const float4*>(h + (size_t)(j0 + da) * DDIM)[l];
            float4 hb = reinterpret_cast<const float4*>(h + (size_t)(j0 + db) * DDIM)[l];
            float4 ra, rb;
            ra.x = (sd0[0] + wself[da] * ha.x) * inv[da] + b4.x;
            ra.y = (sd0[1] + wself[da] * ha.y) * inv[da] + b4.y;
            ra.z = (sd0[2] + wself[da] * ha.z) * inv[da] + b4.z;
            ra.w = (sd0[3] + wself[da] * ha.w) * inv[da] + b4.w;
            rb.x = (sd1[0] + wself[db] * hb.x) * inv[db] + b4.x;
            rb.y = (sd1[1] + wself[db] * hb.y) * inv[db] + b4.y;
            rb.z = (sd1[2] + wself[db] * hb.z) * inv[db] + b4.z;
            rb.w = (sd1[3] + wself[db] * hb.w) * inv[db] + b4.w;
            if (do_relu) {
                ra.x = fmaxf(ra.x, 0.f); ra.y = fmaxf(ra.y, 0.f);
                ra.z = fmaxf(ra.z, 0.f); ra.w = fmaxf(ra.w, 0.f);
                rb.x = fmaxf(rb.x, 0.f); rb.y = fmaxf(rb.y, 0.f);
                rb.z = fmaxf(rb.z, 0.f); rb.w = fmaxf(rb.w, 0.f);
            }
            reinterpret_cast<float4*>(y + (size_t)(j0 + da) * DDIM)[l] = ra;
            reinterpret_cast<float4*>(y + (size_t)(j0 + db) * DDIM)[l] = rb;
        }
    }
}

// ---------------- finalize AB rows: add self, normalize, bias (+relu) ----------------
__global__ void k_fin_ab(float* __restrict__ y, const float* __restrict__ h,
                         const float* __restrict__ als, const float* __restrict__ ald,
                         const float* __restrict__ bias, int do_relu) {
    int idx = blockIdx.x * 256 + threadIdx.x;
    int i = idx >> 7, c = idx & 127;
    float es = __expf(lrelu(als[i] + ald[i]));
    float v = (y[idx] + es * h[idx]) / (g_zsum[i] + es + 1e-16f) + bias[c];
    if (do_relu) v = fmaxf(v, 0.f);
    y[idx] = v;
}

// ---------------- BN stats: AB (single block) + zero AG accumulators ----------------
__global__ void k_stats_ab(const float* __restrict__ gab, const float* __restrict__ bab,
                           const float* __restrict__ ab) {
    int c = threadIdx.x;
    g_sum[c] = 0.f;
    g_ssq[c] = 0.f;
    const float* src = (c < 128) ? (g_z + c) : (ab + c - 128);
    float s = 0.f, ss = 0.f;
    for (int r = 0; r < NAB; r++) {
        float v = src[(size_t)r * DDIM];
        s += v; ss += v * v;
    }
    float mean = s * (1.f / NAB);
    float var = ss * (1.f / NAB) - mean * mean;
    float sc = gab[c] * rsqrtf(var + 1e-5f);
    g_scA[c] = sc;
    g_shA[c] = bab[c] - mean * sc;
}

// ---------------- BN stats: AG partial sums (atomic) ----------------
__global__ void k_stats_ag(const float* __restrict__ ag) {
    int c = threadIdx.x;
    int r0 = blockIdx.x * 64;
    const float* src = (c < 128) ? (g_z + (size_t)(NAB + r0) * DDIM + c)
                                 : (ag + (size_t)r0 * DDIM + c - 128);
    float s = 0.f, ss = 0.f;
    for (int r = 0; r < 64; r++) {
        float v = src[(size_t)r * DDIM];
        s += v; ss += v * v;
    }
    atomicAdd(&g_sum[c], s);
    atomicAdd(&g_ssq[c], ss);
}

__device__ __forceinline__ void bnss(float s, float q, float g, float b, float invn,
                                     float& sc, float& sh) {
    float mean = s * invn;
    float var = q * invn - mean * mean;
    sc = g * rsqrtf(var + 1e-5f);
    sh = b - mean * sc;
}

// ---------------- fused BN -> ReLU -> FC epilogue ----------------
__global__ void k_apply(float* __restrict__ out,
                        const float* __restrict__ ab, const float* __restrict__ ag,
                        const float* __restrict__ fcw, const float* __restrict__ fcb,
                        const float* __restrict__ agw, const float* __restrict__ agb,
                        const float* __restrict__ gag, const float* __restrict__ bag) {
    const int row = blockIdx.x * 8 + (threadIdx.x >> 5);
    const int l = threadIdx.x & 31;
    float4 v1 = reinterpret_cast<const float4*>(g_z + (size_t)row * DDIM)[l];
    float4 v2 = (row < NAB)
        ? reinterpret_cast<const float4*>(ab + (size_t)row * DDIM)[l]
        : reinterpret_cast<const float4*>(ag + (size_t)(row - NAB) * DDIM)[l];
    float4 scA, shAv, scB, shB;
    const float* w;
    float fb;
    if (row < NAB) {
        scA = reinterpret_cast<const float4*>(g_scA)[l];
        shAv = reinterpret_cast<const float4*>(g_shA)[l];
        scB = reinterpret_cast<const float4*>(g_scA)[32 + l];
        shB = reinterpret_cast<const float4*>(g_shA)[32 + l];
        w = fcw; fb = fcb[0];
    } else {
        const float invn = 1.f / (float)NAGN;
        float4 s1 = reinterpret_cast<const float4*>(g_sum)[l];
        float4 q1 = reinterpret_cast<const float4*>(g_ssq)[l];
        float4 s2 = reinterpret_cast<const float4*>(g_sum)[32 + l];
        float4 q2 = reinterpret_cast<const float4*>(g_ssq)[32 + l];
        float4 gA = reinterpret_cast<const float4*>(gag)[l];
        float4 bA = reinterpret_cast<const float4*>(bag)[l];
        float4 gB = reinterpret_cast<const float4*>(gag)[32 + l];
        float4 bB = reinterpret_cast<const float4*>(bag)[32 + l];
        bnss(s1.x, q1.x, gA.x, bA.x, invn, scA.x, shAv.x);
        bnss(s1.y, q1.y, gA.y, bA.y, invn, scA.y, shAv.y);
        bnss(s1.z, q1.z, gA.z, bA.z, invn, scA.z, shAv.z);
        bnss(s1.w, q1.w, gA.w, bA.w, invn, scA.w, shAv.w);
        bnss(s2.x, q2.x, gB.x, bB.x, invn, scB.x, shB.x);
        bnss(s2.y, q2.y, gB.y, bB.y, invn, scB.y, shB.y);
        bnss(s2.z, q2.z, gB.z, bB.z, invn, scB.z, shB.z);
        bnss(s2.w, q2.w, gB.w, bB.w, invn, scB.w, shB.w);
        w = agw; fb = agb[0];
    }
    float4 w1 = reinterpret_cast<const float4*>(w)[l];
    float4 w2 = reinterpret_cast<const float4*>(w)[32 + l];
    float sum = 0.f;
    sum += fmaxf(v1.x * scA.x + shAv.x, 0.f) * w1.x;
    sum += fmaxf(v1.y * scA.y + shAv.y, 0.f) * w1.y;
    sum += fmaxf(v1.z * scA.z + shAv.z, 0.f) * w1.z;
    sum += fmaxf(v1.w * scA.w + shAv.w, 0.f) * w1.w;
    sum += fmaxf(v2.x * scB.x + shB.x, 0.f) * w2.x;
    sum += fmaxf(v2.y * scB.y + shB.y, 0.f) * w2.y;
    sum += fmaxf(v2.z * scB.z + shB.z, 0.f) * w2.z;
    sum += fmaxf(v2.w * scB.w + shB.w, 0.f) * w2.w;
#pragma unroll
    for (int off = 16; off; off >>= 1) sum += __shfl_xor_sync(0xffffffffu, sum, off);
    if (l == 0) out[row] = sum + fb;
}

// ---------------- host ----------------
extern "C" void kernel_launch(void* const* d_in, const int* in_sizes, int n_in,
                              void* d_out, int out_size) {
    const float* ab  = (const float*)d_in[0];
    const float* ag  = (const float*)d_in[1];
    const float* W1  = (const float*)d_in[2];
    const float* as1 = (const float*)d_in[3];
    const float* ad1 = (const float*)d_in[4];
    const float* b1  = (const float*)d_in[5];
    const float* W2  = (const float*)d_in[6];
    const float* as2 = (const float*)d_in[7];
    const float* ad2 = (const float*)d_in[8];
    const float* b2  = (const float*)d_in[9];
    const float* gab = (const float*)d_in[10];
    const float* bab = (const float*)d_in[11];
    const float* gag = (const float*)d_in[12];
    const float* bag = (const float*)d_in[13];
    const float* fcw = (const float*)d_in[14];
    const float* fcb = (const float*)d_in[15];
    const float* agw = (const float*)d_in[16];
    const float* agb = (const float*)d_in[17];
    float* out = (float*)d_out;

    float *ph, *py, *pz, *pals, *pald;
    cudaGetSymbolAddress((void**)&ph, g_h);
    cudaGetSymbolAddress((void**)&py, g_y);
    cudaGetSymbolAddress((void**)&pz, g_z);
    cudaGetSymbolAddress((void**)&pals, g_als);
    cudaGetSymbolAddress((void**)&pald, g_ald);

    const int SMEM_GEMM = (16384 + 8192 + 256) * 4;   // 97 KB
    cudaFuncSetAttribute(k_gemm, cudaFuncAttributeMaxDynamicSharedMemorySize, SMEM_GEMM);

    // ---- layer 1 ----
    k_gemm<<<260, 256, SMEM_GEMM>>>(ab, ag, W1, as1, ad1, ph, pals, pald, py);
    k_agg<<<512, 256>>>(ph, pals, pald, b1, py, 1);
    k_fin_ab<<<128, 256>>>(py, ph, pals, pald, b1, 1);

    // ---- layer 2 ----
    k_gemm<<<260, 256, SMEM_GEMM>>>(py, py + NAB * DDIM, W2, as2, ad2, ph, pals, pald, pz);
    k_agg<<<512, 256>>>(ph, pals, pald, b2, pz, 0);
    k_fin_ab<<<128, 256>>>(pz, ph, pals, pald, b2, 0);

    // ---- BN + FC epilogue ----
    k_stats_ab<<<1, 256>>>(gab, bab, ab);
    k_stats_ag<<<256, 256>>>(ag);
    k_apply<<<2080, 256>>>(out, ab, ag, fcw, fcb, agw, agb, gag, bag);
}

// round 7
// speedup vs baseline: 1.1816x; 1.1816x over previous
#include <cuda_runtime.h>

#define NAB 256
#define NAGN 16384
#define NTOT 16640
#define DDIM 128
#define GSZ 2048

typedef unsigned long long ull;

// ---------------- scratch (device globals; no allocation) ----------------
__device__ float g_h[NTOT * DDIM];
__device__ float g_y[NTOT * DDIM];
__device__ float g_z[NTOT * DDIM];
__device__ float g_als[NTOT];
__device__ float g_ald[NTOT];
__device__ float g_zsum[NAB];
__device__ float g_sum[2 * DDIM];
__device__ float g_ssq[2 * DDIM];
__device__ float g_scA[2 * DDIM];
__device__ float g_shA[2 * DDIM];

__device__ __forceinline__ float lrelu(float e) { return e > 0.f ? e : 0.2f * e; }

// ---- packed f32x2 helpers (Blackwell FFMA2) ----
__device__ __forceinline__ ull dup2(float s) {
    ull d; unsigned u = __float_as_uint(s);
    asm("mov.b64 %0, {%1, %1};" : "=l"(d) : "r"(u));
    return d;
}
__device__ __forceinline__ void ffma2(ull& acc, ull a, ull b) {
    asm("fma.rn.f32x2 %0, %1, %2, %0;" : "+l"(acc) : "l"(a), "l"(b));
}
__device__ __forceinline__ void unpk(float& lo, float& hi, ull v) {
    unsigned a, b;
    asm("mov.b64 {%0, %1}, %2;" : "=r"(a), "=r"(b) : "l"(v));
    lo = __uint_as_float(a); hi = __uint_as_float(b);
}

// ---------------- GEMM: H = X @ W, plus al_src/al_dst row dots ----------------
// 130 blocks x 256 thr (16x16), 128 rows/block, 8x8 thread tile.
__global__ void __launch_bounds__(256, 1)
k_gemm(const float* __restrict__ X0, const float* __restrict__ X1,
       const float* __restrict__ W,
       const float* __restrict__ asrc, const float* __restrict__ adst,
       float* __restrict__ H, float* __restrict__ ALS, float* __restrict__ ALD,
       float* __restrict__ yz) {
    extern __shared__ float sm[];
    float* Ws = sm;                  // 128*128 (k-major, native)
    float* Xs = sm + 16384;          // 128*128 (row-major)
    float* as_sh = sm + 32768;       // 128
    float* ad_sh = sm + 32896;       // 128
    const int t = threadIdx.x;
    const int row0 = blockIdx.x * 128;

    // zero AB region of aggregation target + zsum (blocks 0,1)
    if (row0 < NAB) {
        float4* z4 = reinterpret_cast<float4*>(yz) + row0 * 32;
#pragma unroll
        for (int i = 0; i < 16; i++) z4[t + 256 * i] = make_float4(0.f, 0.f, 0.f, 0.f);
        if (blockIdx.x == 0) g_zsum[t] = 0.f;
    }

    const float* X = (row0 < NAB) ? (X0 + (size_t)row0 * DDIM)
                                  : (X1 + (size_t)(row0 - NAB) * DDIM);

    const float4* W4 = reinterpret_cast<const float4*>(W);
    float4* Ws4s = reinterpret_cast<float4*>(Ws);
#pragma unroll
    for (int i = 0; i < 16; i++) Ws4s[t + 256 * i] = W4[t + 256 * i];
    const float4* Xg4 = reinterpret_cast<const float4*>(X);
    float4* Xs4s = reinterpret_cast<float4*>(Xs);
#pragma unroll
    for (int i = 0; i < 16; i++) Xs4s[t + 256 * i] = Xg4[t + 256 * i];
    if (t < 128) { as_sh[t] = asrc[t]; ad_sh[t] = adst[t]; }
    __syncthreads();

    const int tx = t & 15;      // col group: cols 8*tx .. 8*tx+7
    const int ty = t >> 4;      // row group: rows 8*ty .. 8*ty+7
    ull acc[8][4];              // [row][col-pair]
#pragma unroll
    for (int r = 0; r < 8; r++)
#pragma unroll
        for (int c = 0; c < 4; c++) acc[r][c] = 0ull;

    const ulonglong2* Wsu = reinterpret_cast<const ulonglong2*>(Ws);  // [k][32]
    const float4* Xs4 = reinterpret_cast<const float4*>(Xs);          // [row][32]

#pragma unroll 2
    for (int k0 = 0; k0 < DDIM; k0 += 4) {
        ulonglong2 wa[4], wb[4];
#pragma unroll
        for (int kk = 0; kk < 4; kk++) {
            wa[kk] = Wsu[(k0 + kk) * 32 + 2 * tx];
            wb[kk] = Wsu[(k0 + kk) * 32 + 2 * tx + 1];
        }
#pragma unroll
        for (int r = 0; r < 8; r++) {
            float4 xr = Xs4[(ty * 8 + r) * 32 + (k0 >> 2)];
            ull xd;
            xd = dup2(xr.x);
            ffma2(acc[r][0], xd, wa[0].x); ffma2(acc[r][1], xd, wa[0].y);
            ffma2(acc[r][2], xd, wb[0].x); ffma2(acc[r][3], xd, wb[0].y);
            xd = dup2(xr.y);
            ffma2(acc[r][0], xd, wa[1].x); ffma2(acc[r][1], xd, wa[1].y);
            ffma2(acc[r][2], xd, wb[1].x); ffma2(acc[r][3], xd, wb[1].y);
            xd = dup2(xr.z);
            ffma2(acc[r][0], xd, wa[2].x); ffma2(acc[r][1], xd, wa[2].y);
            ffma2(acc[r][2], xd, wb[2].x); ffma2(acc[r][3], xd, wb[2].y);
            xd = dup2(xr.w);
            ffma2(acc[r][0], xd, wa[3].x); ffma2(acc[r][1], xd, wa[3].y);
            ffma2(acc[r][2], xd, wb[3].x); ffma2(acc[r][3], xd, wb[3].y);
        }
    }

    float4* H4 = reinterpret_cast<float4*>(H + (size_t)row0 * DDIM);
    float4 asa = reinterpret_cast<const float4*>(as_sh)[2 * tx];
    float4 asb = reinterpret_cast<const float4*>(as_sh)[2 * tx + 1];
    float4 ada = reinterpret_cast<const float4*>(ad_sh)[2 * tx];
    float4 adb = reinterpret_cast<const float4*>(ad_sh)[2 * tx + 1];
#pragma unroll
    for (int r = 0; r < 8; r++) {
        const int lrow = ty * 8 + r;
        float4 v1, v2;
        unpk(v1.x, v1.y, acc[r][0]);
        unpk(v1.z, v1.w, acc[r][1]);
        unpk(v2.x, v2.y, acc[r][2]);
        unpk(v2.z, v2.w, acc[r][3]);
        H4[lrow * 32 + 2 * tx] = v1;
        H4[lrow * 32 + 2 * tx + 1] = v2;
        float ps = v1.x * asa.x + v1.y * asa.y + v1.z * asa.z + v1.w * asa.w
                 + v2.x * asb.x + v2.y * asb.y + v2.z * asb.z + v2.w * asb.w;
        float pd = v1.x * ada.x + v1.y * ada.y + v1.z * ada.z + v1.w * ada.w
                 + v2.x * adb.x + v2.y * adb.y + v2.z * adb.z + v2.w * adb.w;
#pragma unroll
        for (int off = 8; off; off >>= 1) {
            ps += __shfl_xor_sync(0xffffffffu, ps, off, 16);
            pd += __shfl_xor_sync(0xffffffffu, pd, off, 16);
        }
        if (tx == 0) {
            ALS[row0 + lrow] = ps;
            ALD[row0 + lrow] = pd;
        }
    }
}

// ---------------- fused aggregation + softmax (no max-shift) ----------------
// blocks 0..255: AB dsts (batch, 256-src chunk, dst-octet), partial sums + z via atomics
// blocks 256..767: AG dsts, fully fused softmax + weighted sum
__global__ void __launch_bounds__(256, 3)
k_agg(const float* __restrict__ h, const float* __restrict__ als,
      const float* __restrict__ ald, const float* __restrict__ bias,
      float* __restrict__ y, int do_relu) {
    __shared__ __align__(16) float sbig[8192];
    __shared__ float4 swT[8][32];
    __shared__ float ssmall[16];
    const int t = threadIdx.x;

    if (blockIdx.x < 256) {
        // -------- AB dsts --------
        const int blk = blockIdx.x;
        const int b = blk >> 5, q = (blk >> 2) & 7, dq = blk & 3;
        const int base = NAB + b * GSZ + q * 256;
        const int d0 = b * 32 + dq * 8;
        float* ald_sh = ssmall;
        float* szs = ssmall + 8;
        if (t < 8) { ald_sh[t] = ald[d0 + t]; szs[t] = 0.f; }
        __syncthreads();
        {
            const int dme = t & 7;
            const float aldme = ald_sh[dme];
            float zloc = 0.f;
#pragma unroll
            for (int i = 0; i < 8; i++) {
                int idx = t + 256 * i;
                int j = idx >> 3;
                float e = __expf(lrelu(als[base + j] + aldme));
                sbig[idx] = e;
                zloc += e;
            }
            atomicAdd(&szs[dme], zloc);
        }
        __syncthreads();
        if (t < 8) atomicAdd(&g_zsum[d0 + t], szs[t]);

        const int c4 = t & 31, rs = t >> 5;
        ull acc2[4][4];
#pragma unroll
        for (int dp = 0; dp < 4; dp++)
#pragma unroll
            for (int c = 0; c < 4; c++) acc2[dp][c] = 0ull;

        const float4* h4 = reinterpret_cast<const float4*>(h) + (size_t)base * 32 + c4;
        const ull* w8 = reinterpret_cast<const ull*>(sbig);
#pragma unroll 4
        for (int jj = 0; jj < 32; jj++) {
            const int j = rs * 32 + jj;
            float4 hv = h4[(size_t)j * 32];
            ull hd0 = dup2(hv.x), hd1 = dup2(hv.y), hd2 = dup2(hv.z), hd3 = dup2(hv.w);
#pragma unroll
            for (int dp = 0; dp < 4; dp++) {
                ull a = w8[j * 4 + dp];
                ffma2(acc2[dp][0], a, hd0); ffma2(acc2[dp][1], a, hd1);
                ffma2(acc2[dp][2], a, hd2); ffma2(acc2[dp][3], a, hd3);
            }
        }
        __syncthreads();
        float4* st4 = reinterpret_cast<float4*>(sbig) + rs * 256;
#pragma unroll
        for (int dp = 0; dp < 4; dp++) {
            float4 ve, vo;
            unpk(ve.x, vo.x, acc2[dp][0]);
            unpk(ve.y, vo.y, acc2[dp][1]);
            unpk(ve.z, vo.z, acc2[dp][2]);
            unpk(ve.w, vo.w, acc2[dp][3]);
            st4[(2 * dp) * 32 + c4] = ve;
            st4[(2 * dp + 1) * 32 + c4] = vo;
        }
        __syncthreads();
        float s0 = 0.f, s1 = 0.f, s2 = 0.f, s3 = 0.f;
#pragma unroll
        for (int rr = 0; rr < 8; rr++) {
            float4 v = reinterpret_cast<const float4*>(sbig)[rr * 256 + t];
            s0 += v.x; s1 += v.y; s2 += v.z; s3 += v.w;
        }
        const int d = t >> 5, c = (t & 31) * 4;
        float* yo = y + (size_t)(d0 + d) * DDIM + c;
        atomicAdd(yo + 0, s0); atomicAdd(yo + 1, s1);
        atomicAdd(yo + 2, s2); atomicAdd(yo + 3, s3);
    } else {
        // -------- AG dsts --------
        const int ablk = blockIdx.x - 256;
        const int b = ablk >> 6, chunk = ablk & 63;
        {
            const float4* hsrc = reinterpret_cast<const float4*>(h + (size_t)b * 32 * DDIM);
            float4* hd = reinterpret_cast<float4*>(sbig);
#pragma unroll
            for (int i = 0; i < 4; i++) hd[t + 256 * i] = hsrc[t + 256 * i];
        }
        __shared__ float als_sh[32];
        if (t < 32) als_sh[t] = als[b * 32 + t];
        __syncthreads();
        const int w = t >> 5, l = t & 31;
        const int j0 = NAB + b * GSZ + chunk * 32 + w * 4;

        float wv[4], inv[4], wself[4];
#pragma unroll
        for (int d = 0; d < 4; d++) {
            float aldv = ald[j0 + d];
            wv[d] = __expf(lrelu(als_sh[l] + aldv));
            wself[d] = __expf(lrelu(als[j0 + d] + aldv));
            float s = wv[d];
#pragma unroll
            for (int off = 16; off; off >>= 1) s += __shfl_xor_sync(0xffffffffu, s, off);
            inv[d] = 1.f / (s + wself[d] + 1e-16f);
        }
        swT[w][l] = make_float4(wv[0], wv[1], wv[2], wv[3]);
        __syncwarp();

        ull acc01[4], acc23[4];
#pragma unroll
        for (int c = 0; c < 4; c++) { acc01[c] = 0ull; acc23[c] = 0ull; }

        const float4* hab4 = reinterpret_cast<const float4*>(sbig);
        const ulonglong2* swu = reinterpret_cast<const ulonglong2*>(&swT[w][0]);
#pragma unroll 8
        for (int l2 = 0; l2 < 32; l2++) {
            ulonglong2 wq = swu[l2];
            float4 hv = hab4[l2 * 32 + l];
            ull hd;
            hd = dup2(hv.x); ffma2(acc01[0], wq.x, hd); ffma2(acc23[0], wq.y, hd);
            hd = dup2(hv.y); ffma2(acc01[1], wq.x, hd); ffma2(acc23[1], wq.y, hd);
            hd = dup2(hv.z); ffma2(acc01[2], wq.x, hd); ffma2(acc23[2], wq.y, hd);
            hd = dup2(hv.w); ffma2(acc01[3], wq.x, hd); ffma2(acc23[3], wq.y, hd);
        }
        float sd[4][4];
#pragma unroll
        for (int c = 0; c < 4; c++) {
            unpk(sd[0][c], sd[1][c], acc01[c]);
            unpk(sd[2][c], sd[3][c], acc23[c]);
        }
        float4 b4 = reinterpret_cast<const float4*>(bias)[l];
#pragma unroll
        for (int d = 0; d < 4; d++) {
            float4 hs = reinterpret_cast<const float4*>(h + (size_t)(j0 + d) * DDIM)[l];
            float4 r;
            r.x = (sd[d][0] + wself[d] * hs.x) * inv[d] + b4.x;
            r.y = (sd[d][1] + wself[d] * hs.y) * inv[d] + b4.y;
            r.z = (sd[d][2] + wself[d] * hs.z) * inv[d] + b4.z;
            r.w = (sd[d][3] + wself[d] * hs.w) * inv[d] + b4.w;
            if (do_relu) {
                r.x = fmaxf(r.x, 0.f); r.y = fmaxf(r.y, 0.f);
                r.z = fmaxf(r.z, 0.f); r.w = fmaxf(r.w, 0.f);
            }
            reinterpret_cast<float4*>(y + (size_t)(j0 + d) * DDIM)[l] = r;
        }
    }
}

// ---------------- finalize AB rows ----------------
__global__ void k_fin_ab(float* __restrict__ y, const float* __restrict__ h,
                         const float* __restrict__ als, const float* __restrict__ ald,
                         const float* __restrict__ bias, int do_relu) {
    int idx = blockIdx.x * 256 + threadIdx.x;
    int i = idx >> 7, c = idx & 127;
    float es = __expf(lrelu(als[i] + ald[i]));
    float v = (y[idx] + es * h[idx]) / (g_zsum[i] + es + 1e-16f) + bias[c];
    if (do_relu) v = fmaxf(v, 0.f);
    y[idx] = v;
}

// ---------------- BN stats: AB (single block) + zero AG accumulators ----------------
__global__ void k_stats_ab(const float* __restrict__ gab, const float* __restrict__ bab,
                           const float* __restrict__ ab) {
    int c = threadIdx.x;
    g_sum[c] = 0.f;
    g_ssq[c] = 0.f;
    const float* src = (c < 128) ? (g_z + c) : (ab + c - 128);
    float s = 0.f, ss = 0.f;
    for (int r = 0; r < NAB; r++) {
        float v = src[(size_t)r * DDIM];
        s += v; ss += v * v;
    }
    float mean = s * (1.f / NAB);
    float var = ss * (1.f / NAB) - mean * mean;
    float sc = gab[c] * rsqrtf(var + 1e-5f);
    g_scA[c] = sc;
    g_shA[c] = bab[c] - mean * sc;
}

// ---------------- BN stats: AG partial sums (atomic) ----------------
__global__ void k_stats_ag(const float* __restrict__ ag) {
    int c = threadIdx.x;
    int r0 = blockIdx.x * 64;
    const float* src = (c < 128) ? (g_z + (size_t)(NAB + r0) * DDIM + c)
                                 : (ag + (size_t)r0 * DDIM + c - 128);
    float s = 0.f, ss = 0.f;
    for (int r = 0; r < 64; r++) {
        float v = src[(size_t)r * DDIM];
        s += v; ss += v * v;
    }
    atomicAdd(&g_sum[c], s);
    atomicAdd(&g_ssq[c], ss);
}

__device__ __forceinline__ void bnss(float s, float q, float g, float b, float invn,
                                     float& sc, float& sh) {
    float mean = s * invn;
    float var = q * invn - mean * mean;
    sc = g * rsqrtf(var + 1e-5f);
    sh = b - mean * sc;
}

// ---------------- fused BN -> ReLU -> FC epilogue ----------------
__global__ void k_apply(float* __restrict__ out,
                        const float* __restrict__ ab, const float* __restrict__ ag,
                        const float* __restrict__ fcw, const float* __restrict__ fcb,
                        const float* __restrict__ agw, const float* __restrict__ agb,
                        const float* __restrict__ gag, const float* __restrict__ bag) {
    const int row = blockIdx.x * 8 + (threadIdx.x >> 5);
    const int l = threadIdx.x & 31;
    float4 v1 = reinterpret_cast<const float4*>(g_z + (size_t)row * DDIM)[l];
    float4 v2 = (row < NAB)
        ? reinterpret_cast<const float4*>(ab + (size_t)row * DDIM)[l]
        : reinterpret_cast<const float4*>(ag + (size_t)(row - NAB) * DDIM)[l];
    float4 scA, shAv, scB, shB;
    const float* w;
    float fb;
    if (row < NAB) {
        scA = reinterpret_cast<const float4*>(g_scA)[l];
        shAv = reinterpret_cast<const float4*>(g_shA)[l];
        scB = reinterpret_cast<const float4*>(g_scA)[32 + l];
        shB = reinterpret_cast<const float4*>(g_shA)[32 + l];
        w = fcw; fb = fcb[0];
    } else {
        const float invn = 1.f / (float)NAGN;
        float4 s1 = reinterpret_cast<const float4*>(g_sum)[l];
        float4 q1 = reinterpret_cast<const float4*>(g_ssq)[l];
        float4 s2 = reinterpret_cast<const float4*>(g_sum)[32 + l];
        float4 q2 = reinterpret_cast<const float4*>(g_ssq)[32 + l];
        float4 gA = reinterpret_cast<const float4*>(gag)[l];
        float4 bA = reinterpret_cast<const float4*>(bag)[l];
        float4 gB = reinterpret_cast<const float4*>(gag)[32 + l];
        float4 bB = reinterpret_cast<const float4*>(bag)[32 + l];
        bnss(s1.x, q1.x, gA.x, bA.x, invn, scA.x, shAv.x);
        bnss(s1.y, q1.y, gA.y, bA.y, invn, scA.y, shAv.y);
        bnss(s1.z, q1.z, gA.z, bA.z, invn, scA.z, shAv.z);
        bnss(s1.w, q1.w, gA.w, bA.w, invn, scA.w, shAv.w);
        bnss(s2.x, q2.x, gB.x, bB.x, invn, scB.x, shB.x);
        bnss(s2.y, q2.y, gB.y, bB.y, invn, scB.y, shB.y);
        bnss(s2.z, q2.z, gB.z, bB.z, invn, scB.z, shB.z);
        bnss(s2.w, q2.w, gB.w, bB.w, invn, scB.w, shB.w);
        w = agw; fb = agb[0];
    }
    float4 w1 = reinterpret_cast<const float4*>(w)[l];
    float4 w2 = reinterpret_cast<const float4*>(w)[32 + l];
    float sum = 0.f;
    sum += fmaxf(v1.x * scA.x + shAv.x, 0.f) * w1.x;
    sum += fmaxf(v1.y * scA.y + shAv.y, 0.f) * w1.y;
    sum += fmaxf(v1.z * scA.z + shAv.z, 0.f) * w1.z;
    sum += fmaxf(v1.w * scA.w + shAv.w, 0.f) * w1.w;
    sum += fmaxf(v2.x * scB.x + shB.x, 0.f) * w2.x;
    sum += fmaxf(v2.y * scB.y + shB.y, 0.f) * w2.y;
    sum += fmaxf(v2.z * scB.z + shB.z, 0.f) * w2.z;
    sum += fmaxf(v2.w * scB.w + shB.w, 0.f) * w2.w;
#pragma unroll
    for (int off = 16; off; off >>= 1) sum += __shfl_xor_sync(0xffffffffu, sum, off);
    if (l == 0) out[row] = sum + fb;
}

// ---------------- host ----------------
extern "C" void kernel_launch(void* const* d_in, const int* in_sizes, int n_in,
                              void* d_out, int out_size) {
    const float* ab  = (const float*)d_in[0];
    const float* ag  = (const float*)d_in[1];
    const float* W1  = (const float*)d_in[2];
    const float* as1 = (const float*)d_in[3];
    const float* ad1 = (const float*)d_in[4];
    const float* b1  = (const float*)d_in[5];
    const float* W2  = (const float*)d_in[6];
    const float* as2 = (const float*)d_in[7];
    const float* ad2 = (const float*)d_in[8];
    const float* b2  = (const float*)d_in[9];
    const float* gab = (const float*)d_in[10];
    const float* bab = (const float*)d_in[11];
    const float* gag = (const float*)d_in[12];
    const float* bag = (const float*)d_in[13];
    const float* fcw = (const float*)d_in[14];
    const float* fcb = (const float*)d_in[15];
    const float* agw = (const float*)d_in[16];
    const float* agb = (const float*)d_in[17];
    float* out = (float*)d_out;

    float *ph, *py, *pz, *pals, *pald;
    cudaGetSymbolAddress((void**)&ph, g_h);
    cudaGetSymbolAddress((void**)&py, g_y);
    cudaGetSymbolAddress((void**)&pz, g_z);
    cudaGetSymbolAddress((void**)&pals, g_als);
    cudaGetSymbolAddress((void**)&pald, g_ald);

    const int SMEM_GEMM = (16384 + 16384 + 256) * 4;   // 129 KB
    cudaFuncSetAttribute(k_gemm, cudaFuncAttributeMaxDynamicSharedMemorySize, SMEM_GEMM);

    // ---- layer 1 ----
    k_gemm<<<130, 256, SMEM_GEMM>>>(ab, ag, W1, as1, ad1, ph, pals, pald, py);
    k_agg<<<768, 256>>>(ph, pals, pald, b1, py, 1);
    k_fin_ab<<<128, 256>>>(py, ph, pals, pald, b1, 1);

    // ---- layer 2 ----
    k_gemm<<<130, 256, SMEM_GEMM>>>(py, py + NAB * DDIM, W2, as2, ad2, ph, pals, pald, pz);
    k_agg<<<768, 256>>>(ph, pals, pald, b2, pz, 0);
    k_fin_ab<<<128, 256>>>(pz, ph, pals, pald, b2, 0);

    // ---- BN + FC epilogue ----
    k_stats_ab<<<1, 256>>>(gab, bab, ab);
    k_stats_ag<<<256, 256>>>(ag);
    k_apply<<<2080, 256>>>(out, ab, ag, fcw, fcb, agw, agb, gag, bag);
}

// round 8
// speedup vs baseline: 1.2125x; 1.0262x over previous
#include <cuda_runtime.h>

#define NAB 256
#define NAGN 16384
#define NTOT 16640
#define DDIM 128
#define GSZ 2048

typedef unsigned long long ull;

// ---------------- scratch (device globals; no allocation) ----------------
__device__ float g_h[NTOT * DDIM];
__device__ float g_y[NTOT * DDIM];
__device__ float g_z[NTOT * DDIM];
__device__ float g_als[NTOT];
__device__ float g_ald[NTOT];
__device__ float g_zsum[NAB];
__device__ float g_sum[2 * DDIM];
__device__ float g_ssq[2 * DDIM];
__device__ float g_sumAB[2 * DDIM];
__device__ float g_ssqAB[2 * DDIM];

__device__ __forceinline__ float lrelu(float e) { return e > 0.f ? e : 0.2f * e; }

// ---- packed f32x2 helpers (Blackwell FFMA2) ----
__device__ __forceinline__ ull dup2(float s) {
    ull d; unsigned u = __float_as_uint(s);
    asm("mov.b64 %0, {%1, %1};" : "=l"(d) : "r"(u));
    return d;
}
__device__ __forceinline__ void ffma2(ull& acc, ull a, ull b) {
    asm("fma.rn.f32x2 %0, %1, %2, %0;" : "+l"(acc) : "l"(a), "l"(b));
}
__device__ __forceinline__ void unpk(float& lo, float& hi, ull v) {
    unsigned a, b;
    asm("mov.b64 {%0, %1}, %2;" : "=r"(a), "=r"(b) : "l"(v));
    lo = __uint_as_float(a); hi = __uint_as_float(b);
}

// ---------------- GEMM: H = X @ W, plus al_src/al_dst row dots ----------------
// 260 blocks x 128 thr, 64 rows/block, 8x8 thread tile.
// W streamed from GMEM through L1 (same addresses across all warps/CTAs -> L1 hits).
__global__ void __launch_bounds__(128, 3)
k_gemm(const float* __restrict__ X0, const float* __restrict__ X1,
       const float* __restrict__ W,
       const float* __restrict__ asrc, const float* __restrict__ adst,
       float* __restrict__ H, float* __restrict__ ALS, float* __restrict__ ALD,
       float* __restrict__ yz) {
    __shared__ __align__(16) float Xs[64 * DDIM];
    __shared__ float as_sh[128], ad_sh[128];
    const int t = threadIdx.x;
    const int row0 = blockIdx.x * 64;

    // zero AB region of aggregation target + zsum (blocks 0..3)
    if (row0 < NAB) {
        float4* z4 = reinterpret_cast<float4*>(yz) + row0 * 32;
#pragma unroll
        for (int i = 0; i < 16; i++) z4[t + 128 * i] = make_float4(0.f, 0.f, 0.f, 0.f);
        if (blockIdx.x == 0) { g_zsum[t] = 0.f; g_zsum[t + 128] = 0.f; }
    }

    const float* X = (row0 < NAB) ? (X0 + (size_t)row0 * DDIM)
                                  : (X1 + (size_t)(row0 - NAB) * DDIM);
    const float4* Xg4 = reinterpret_cast<const float4*>(X);
    float4* Xs4s = reinterpret_cast<float4*>(Xs);
#pragma unroll
    for (int i = 0; i < 16; i++) Xs4s[t + 128 * i] = Xg4[t + 128 * i];
    as_sh[t] = asrc[t];
    ad_sh[t] = adst[t];
    __syncthreads();

    const int tx = t & 15;      // col group: cols 8*tx .. 8*tx+7
    const int ty = t >> 4;      // row group: rows 8*ty .. 8*ty+7
    ull acc[8][4];              // [row][col-pair]
#pragma unroll
    for (int r = 0; r < 8; r++)
#pragma unroll
        for (int c = 0; c < 4; c++) acc[r][c] = 0ull;

    const ulonglong2* Wg = reinterpret_cast<const ulonglong2*>(W);   // [k][32]
    const float4* Xs4 = reinterpret_cast<const float4*>(Xs);         // [row][32]

#pragma unroll 2
    for (int k0 = 0; k0 < DDIM; k0 += 4) {
        ulonglong2 wa[4], wb[4];
#pragma unroll
        for (int kk = 0; kk < 4; kk++) {
            wa[kk] = Wg[(k0 + kk) * 32 + 2 * tx];
            wb[kk] = Wg[(k0 + kk) * 32 + 2 * tx + 1];
        }
#pragma unroll
        for (int r = 0; r < 8; r++) {
            float4 xr = Xs4[(ty * 8 + r) * 32 + (k0 >> 2)];
            ull xd;
            xd = dup2(xr.x);
            ffma2(acc[r][0], xd, wa[0].x); ffma2(acc[r][1], xd, wa[0].y);
            ffma2(acc[r][2], xd, wb[0].x); ffma2(acc[r][3], xd, wb[0].y);
            xd = dup2(xr.y);
            ffma2(acc[r][0], xd, wa[1].x); ffma2(acc[r][1], xd, wa[1].y);
            ffma2(acc[r][2], xd, wb[1].x); ffma2(acc[r][3], xd, wb[1].y);
            xd = dup2(xr.z);
            ffma2(acc[r][0], xd, wa[2].x); ffma2(acc[r][1], xd, wa[2].y);
            ffma2(acc[r][2], xd, wb[2].x); ffma2(acc[r][3], xd, wb[2].y);
            xd = dup2(xr.w);
            ffma2(acc[r][0], xd, wa[3].x); ffma2(acc[r][1], xd, wa[3].y);
            ffma2(acc[r][2], xd, wb[3].x); ffma2(acc[r][3], xd, wb[3].y);
        }
    }

    float4* H4 = reinterpret_cast<float4*>(H + (size_t)row0 * DDIM);
    float4 asa = reinterpret_cast<const float4*>(as_sh)[2 * tx];
    float4 asb = reinterpret_cast<const float4*>(as_sh)[2 * tx + 1];
    float4 ada = reinterpret_cast<const float4*>(ad_sh)[2 * tx];
    float4 adb = reinterpret_cast<const float4*>(ad_sh)[2 * tx + 1];
#pragma unroll
    for (int r = 0; r < 8; r++) {
        const int lrow = ty * 8 + r;
        float4 v1, v2;
        unpk(v1.x, v1.y, acc[r][0]);
        unpk(v1.z, v1.w, acc[r][1]);
        unpk(v2.x, v2.y, acc[r][2]);
        unpk(v2.z, v2.w, acc[r][3]);
        H4[lrow * 32 + 2 * tx] = v1;
        H4[lrow * 32 + 2 * tx + 1] = v2;
        float ps = v1.x * asa.x + v1.y * asa.y + v1.z * asa.z + v1.w * asa.w
                 + v2.x * asb.x + v2.y * asb.y + v2.z * asb.z + v2.w * asb.w;
        float pd = v1.x * ada.x + v1.y * ada.y + v1.z * ada.z + v1.w * ada.w
                 + v2.x * adb.x + v2.y * adb.y + v2.z * adb.z + v2.w * adb.w;
#pragma unroll
        for (int off = 8; off; off >>= 1) {
            ps += __shfl_xor_sync(0xffffffffu, ps, off, 16);
            pd += __shfl_xor_sync(0xffffffffu, pd, off, 16);
        }
        if (tx == 0) {
            ALS[row0 + lrow] = ps;
            ALD[row0 + lrow] = pd;
        }
    }
}

// ---------------- fused aggregation + softmax (no max-shift) ----------------
// blocks 0..255: AB dsts (batch, 256-src chunk, dst-octet), partial sums + z via atomics
// blocks 256..767: AG dsts, fully fused softmax + weighted sum
__global__ void __launch_bounds__(256, 3)
k_agg(const float* __restrict__ h, const float* __restrict__ als,
      const float* __restrict__ ald, const float* __restrict__ bias,
      float* __restrict__ y, int do_relu) {
    __shared__ __align__(16) float sbig[8192];
    __shared__ float4 swT[8][32];
    __shared__ float ssmall[16];
    const int t = threadIdx.x;

    if (blockIdx.x < 256) {
        // -------- AB dsts --------
        const int blk = blockIdx.x;
        const int b = blk >> 5, q = (blk >> 2) & 7, dq = blk & 3;
        const int base = NAB + b * GSZ + q * 256;
        const int d0 = b * 32 + dq * 8;
        float* ald_sh = ssmall;
        float* szs = ssmall + 8;
        if (t < 8) { ald_sh[t] = ald[d0 + t]; szs[t] = 0.f; }
        __syncthreads();
        {
            const int dme = t & 7;
            const float aldme = ald_sh[dme];
            float zloc = 0.f;
#pragma unroll
            for (int i = 0; i < 8; i++) {
                int idx = t + 256 * i;
                int j = idx >> 3;
                float e = __expf(lrelu(als[base + j] + aldme));
                sbig[idx] = e;
                zloc += e;
            }
            atomicAdd(&szs[dme], zloc);
        }
        __syncthreads();
        if (t < 8) atomicAdd(&g_zsum[d0 + t], szs[t]);

        const int c4 = t & 31, rs = t >> 5;
        ull acc2[4][4];
#pragma unroll
        for (int dp = 0; dp < 4; dp++)
#pragma unroll
            for (int c = 0; c < 4; c++) acc2[dp][c] = 0ull;

        const float4* h4 = reinterpret_cast<const float4*>(h) + (size_t)base * 32 + c4;
        const ull* w8 = reinterpret_cast<const ull*>(sbig);
#pragma unroll 8
        for (int jj = 0; jj < 32; jj++) {
            const int j = rs * 32 + jj;
            float4 hv = h4[(size_t)j * 32];
            ull hd0 = dup2(hv.x), hd1 = dup2(hv.y), hd2 = dup2(hv.z), hd3 = dup2(hv.w);
#pragma unroll
            for (int dp = 0; dp < 4; dp++) {
                ull a = w8[j * 4 + dp];
                ffma2(acc2[dp][0], a, hd0); ffma2(acc2[dp][1], a, hd1);
                ffma2(acc2[dp][2], a, hd2); ffma2(acc2[dp][3], a, hd3);
            }
        }
        __syncthreads();
        float4* st4 = reinterpret_cast<float4*>(sbig) + rs * 256;
#pragma unroll
        for (int dp = 0; dp < 4; dp++) {
            float4 ve, vo;
            unpk(ve.x, vo.x, acc2[dp][0]);
            unpk(ve.y, vo.y, acc2[dp][1]);
            unpk(ve.z, vo.z, acc2[dp][2]);
            unpk(ve.w, vo.w, acc2[dp][3]);
            st4[(2 * dp) * 32 + c4] = ve;
            st4[(2 * dp + 1) * 32 + c4] = vo;
        }
        __syncthreads();
        float s0 = 0.f, s1 = 0.f, s2 = 0.f, s3 = 0.f;
#pragma unroll
        for (int rr = 0; rr < 8; rr++) {
            float4 v = reinterpret_cast<const float4*>(sbig)[rr * 256 + t];
            s0 += v.x; s1 += v.y; s2 += v.z; s3 += v.w;
        }
        const int d = t >> 5, c = (t & 31) * 4;
        float* yo = y + (size_t)(d0 + d) * DDIM + c;
        atomicAdd(yo + 0, s0); atomicAdd(yo + 1, s1);
        atomicAdd(yo + 2, s2); atomicAdd(yo + 3, s3);
    } else {
        // -------- AG dsts --------
        const int ablk = blockIdx.x - 256;
        const int b = ablk >> 6, chunk = ablk & 63;
        {
            const float4* hsrc = reinterpret_cast<const float4*>(h + (size_t)b * 32 * DDIM);
            float4* hd = reinterpret_cast<float4*>(sbig);
#pragma unroll
            for (int i = 0; i < 4; i++) hd[t + 256 * i] = hsrc[t + 256 * i];
        }
        __shared__ float als_sh[32];
        if (t < 32) als_sh[t] = als[b * 32 + t];
        __syncthreads();
        const int w = t >> 5, l = t & 31;
        const int j0 = NAB + b * GSZ + chunk * 32 + w * 4;

        float wv[4], inv[4], wself[4];
#pragma unroll
        for (int d = 0; d < 4; d++) {
            float aldv = ald[j0 + d];
            wv[d] = __expf(lrelu(als_sh[l] + aldv));
            wself[d] = __expf(lrelu(als[j0 + d] + aldv));
            float s = wv[d];
#pragma unroll
            for (int off = 16; off; off >>= 1) s += __shfl_xor_sync(0xffffffffu, s, off);
            inv[d] = 1.f / (s + wself[d] + 1e-16f);
        }
        swT[w][l] = make_float4(wv[0], wv[1], wv[2], wv[3]);
        __syncwarp();

        ull acc01[4], acc23[4];
#pragma unroll
        for (int c = 0; c < 4; c++) { acc01[c] = 0ull; acc23[c] = 0ull; }

        const float4* hab4 = reinterpret_cast<const float4*>(sbig);
        const ulonglong2* swu = reinterpret_cast<const ulonglong2*>(&swT[w][0]);
#pragma unroll 8
        for (int l2 = 0; l2 < 32; l2++) {
            ulonglong2 wq = swu[l2];
            float4 hv = hab4[l2 * 32 + l];
            ull hd;
            hd = dup2(hv.x); ffma2(acc01[0], wq.x, hd); ffma2(acc23[0], wq.y, hd);
            hd = dup2(hv.y); ffma2(acc01[1], wq.x, hd); ffma2(acc23[1], wq.y, hd);
            hd = dup2(hv.z); ffma2(acc01[2], wq.x, hd); ffma2(acc23[2], wq.y, hd);
            hd = dup2(hv.w); ffma2(acc01[3], wq.x, hd); ffma2(acc23[3], wq.y, hd);
        }
        float sd[4][4];
#pragma unroll
        for (int c = 0; c < 4; c++) {
            unpk(sd[0][c], sd[1][c], acc01[c]);
            unpk(sd[2][c], sd[3][c], acc23[c]);
        }
        float4 b4 = reinterpret_cast<const float4*>(bias)[l];
#pragma unroll
        for (int d = 0; d < 4; d++) {
            float4 hs = reinterpret_cast<const float4*>(h + (size_t)(j0 + d) * DDIM)[l];
            float4 r;
            r.x = (sd[d][0] + wself[d] * hs.x) * inv[d] + b4.x;
            r.y = (sd[d][1] + wself[d] * hs.y) * inv[d] + b4.y;
            r.z = (sd[d][2] + wself[d] * hs.z) * inv[d] + b4.z;
            r.w = (sd[d][3] + wself[d] * hs.w) * inv[d] + b4.w;
            if (do_relu) {
                r.x = fmaxf(r.x, 0.f); r.y = fmaxf(r.y, 0.f);
                r.z = fmaxf(r.z, 0.f); r.w = fmaxf(r.w, 0.f);
            }
            reinterpret_cast<float4*>(y + (size_t)(j0 + d) * DDIM)[l] = r;
        }
    }
}

// ---------------- finalize AB rows + zero BN accumulators ----------------
__global__ void k_fin_ab(float* __restrict__ y, const float* __restrict__ h,
                         const float* __restrict__ als, const float* __restrict__ ald,
                         const float* __restrict__ bias, int do_relu) {
    int idx = blockIdx.x * 256 + threadIdx.x;
    if (blockIdx.x == 0) {
        g_sum[threadIdx.x] = 0.f;   g_ssq[threadIdx.x] = 0.f;
        g_sumAB[threadIdx.x] = 0.f; g_ssqAB[threadIdx.x] = 0.f;
    }
    int i = idx >> 7, c = idx & 127;
    float es = __expf(lrelu(als[i] + ald[i]));
    float v = (y[idx] + es * h[idx]) / (g_zsum[i] + es + 1e-16f) + bias[c];
    if (do_relu) v = fmaxf(v, 0.f);
    y[idx] = v;
}

// ---------------- BN stats: AB (blocks 0..3) + AG (blocks 4..259), atomics ----------------
__global__ void k_stats(const float* __restrict__ ab, const float* __restrict__ ag) {
    int c = threadIdx.x;
    float s = 0.f, ss = 0.f;
    if (blockIdx.x < 4) {
        int r0 = blockIdx.x * 64;
        const float* src = (c < 128) ? (g_z + (size_t)r0 * DDIM + c)
                                     : (ab + (size_t)r0 * DDIM + c - 128);
        for (int r = 0; r < 64; r++) {
            float v = src[(size_t)r * DDIM];
            s += v; ss += v * v;
        }
        atomicAdd(&g_sumAB[c], s);
        atomicAdd(&g_ssqAB[c], ss);
    } else {
        int r0 = (blockIdx.x - 4) * 64;
        const float* src = (c < 128) ? (g_z + (size_t)(NAB + r0) * DDIM + c)
                                     : (ag + (size_t)r0 * DDIM + c - 128);
        for (int r = 0; r < 64; r++) {
            float v = src[(size_t)r * DDIM];
            s += v; ss += v * v;
        }
        atomicAdd(&g_sum[c], s);
        atomicAdd(&g_ssq[c], ss);
    }
}

__device__ __forceinline__ void bnss(float s, float q, float g, float b, float invn,
                                     float& sc, float& sh) {
    float mean = s * invn;
    float var = q * invn - mean * mean;
    sc = g * rsqrtf(var + 1e-5f);
    sh = b - mean * sc;
}

// ---------------- fused BN -> ReLU -> FC epilogue ----------------
__global__ void k_apply(float* __restrict__ out,
                        const float* __restrict__ ab, const float* __restrict__ ag,
                        const float* __restrict__ fcw, const float* __restrict__ fcb,
                        const float* __restrict__ agw, const float* __restrict__ agb,
                        const float* __restrict__ gab, const float* __restrict__ bab,
                        const float* __restrict__ gag, const float* __restrict__ bag) {
    const int row = blockIdx.x * 8 + (threadIdx.x >> 5);
    const int l = threadIdx.x & 31;
    float4 v1 = reinterpret_cast<const float4*>(g_z + (size_t)row * DDIM)[l];
    float4 v2 = (row < NAB)
        ? reinterpret_cast<const float4*>(ab + (size_t)row * DDIM)[l]
        : reinterpret_cast<const float4*>(ag + (size_t)(row - NAB) * DDIM)[l];

    const float* psum; const float* pssq; const float* pg; const float* pb;
    const float* w; float fb; float invn;
    if (row < NAB) {
        psum = g_sumAB; pssq = g_ssqAB; pg = gab; pb = bab;
        w = fcw; fb = fcb[0]; invn = 1.f / (float)NAB;
    } else {
        psum = g_sum; pssq = g_ssq; pg = gag; pb = bag;
        w = agw; fb = agb[0]; invn = 1.f / (float)NAGN;
    }
    float4 s1 = reinterpret_cast<const float4*>(psum)[l];
    float4 q1 = reinterpret_cast<const float4*>(pssq)[l];
    float4 s2 = reinterpret_cast<const float4*>(psum)[32 + l];
    float4 q2 = reinterpret_cast<const float4*>(pssq)[32 + l];
    float4 gA = reinterpret_cast<const float4*>(pg)[l];
    float4 bA = reinterpret_cast<const float4*>(pb)[l];
    float4 gB = reinterpret_cast<const float4*>(pg)[32 + l];
    float4 bB = reinterpret_cast<const float4*>(pb)[32 + l];
    float4 scA, shAv, scB, shB;
    bnss(s1.x, q1.x, gA.x, bA.x, invn, scA.x, shAv.x);
    bnss(s1.y, q1.y, gA.y, bA.y, invn, scA.y, shAv.y);
    bnss(s1.z, q1.z, gA.z, bA.z, invn, scA.z, shAv.z);
    bnss(s1.w, q1.w, gA.w, bA.w, invn, scA.w, shAv.w);
    bnss(s2.x, q2.x, gB.x, bB.x, invn, scB.x, shB.x);
    bnss(s2.y, q2.y, gB.y, bB.y, invn, scB.y, shB.y);
    bnss(s2.z, q2.z, gB.z, bB.z, invn, scB.z, shB.z);
    bnss(s2.w, q2.w, gB.w, bB.w, invn, scB.w, shB.w);

    float4 w1 = reinterpret_cast<const float4*>(w)[l];
    float4 w2 = reinterpret_cast<const float4*>(w)[32 + l];
    float sum = 0.f;
    sum += fmaxf(v1.x * scA.x + shAv.x, 0.f) * w1.x;
    sum += fmaxf(v1.y * scA.y + shAv.y, 0.f) * w1.y;
    sum += fmaxf(v1.z * scA.z + shAv.z, 0.f) * w1.z;
    sum += fmaxf(v1.w * scA.w + shAv.w, 0.f) * w1.w;
    sum += fmaxf(v2.x * scB.x + shB.x, 0.f) * w2.x;
    sum += fmaxf(v2.y * scB.y + shB.y, 0.f) * w2.y;
    sum += fmaxf(v2.z * scB.z + shB.z, 0.f) * w2.z;
    sum += fmaxf(v2.w * scB.w + shB.w, 0.f) * w2.w;
#pragma unroll
    for (int off = 16; off; off >>= 1) sum += __shfl_xor_sync(0xffffffffu, sum, off);
    if (l == 0) out[row] = sum + fb;
}

// ---------------- host ----------------
extern "C" void kernel_launch(void* const* d_in, const int* in_sizes, int n_in,
                              void* d_out, int out_size) {
    const float* ab  = (const float*)d_in[0];
    const float* ag  = (const float*)d_in[1];
    const float* W1  = (const float*)d_in[2];
    const float* as1 = (const float*)d_in[3];
    const float* ad1 = (const float*)d_in[4];
    const float* b1  = (const float*)d_in[5];
    const float* W2  = (const float*)d_in[6];
    const float* as2 = (const float*)d_in[7];
    const float* ad2 = (const float*)d_in[8];
    const float* b2  = (const float*)d_in[9];
    const float* gab = (const float*)d_in[10];
    const float* bab = (const float*)d_in[11];
    const float* gag = (const float*)d_in[12];
    const float* bag = (const float*)d_in[13];
    const float* fcw = (const float*)d_in[14];
    const float* fcb = (const float*)d_in[15];
    const float* agw = (const float*)d_in[16];
    const float* agb = (const float*)d_in[17];
    float* out = (float*)d_out;

    float *ph, *py, *pz, *pals, *pald;
    cudaGetSymbolAddress((void**)&ph, g_h);
    cudaGetSymbolAddress((void**)&py, g_y);
    cudaGetSymbolAddress((void**)&pz, g_z);
    cudaGetSymbolAddress((void**)&pals, g_als);
    cudaGetSymbolAddress((void**)&pald, g_ald);

    // ---- layer 1 ----
    k_gemm<<<260, 128>>>(ab, ag, W1, as1, ad1, ph, pals, pald, py);
    k_agg<<<768, 256>>>(ph, pals, pald, b1, py, 1);
    k_fin_ab<<<128, 256>>>(py, ph, pals, pald, b1, 1);

    // ---- layer 2 ----
    k_gemm<<<260, 128>>>(py, py + NAB * DDIM, W2, as2, ad2, ph, pals, pald, pz);
    k_agg<<<768, 256>>>(ph, pals, pald, b2, pz, 0);
    k_fin_ab<<<128, 256>>>(pz, ph, pals, pald, b2, 0);

    // ---- BN + FC epilogue ----
    k_stats<<<260, 256>>>(ab, ag);
    k_apply<<<2080, 256>>>(out, ab, ag, fcw, fcb, agw, agb, gab, bab, gag, bag);
}

// round 9
// speedup vs baseline: 1.3897x; 1.1461x over previous
#include <cuda_runtime.h>
#include <cuda_bf16.h>

#define NAB 256
#define NAGN 16384
#define NTOT 16640
#define DDIM 128
#define GSZ 2048

typedef unsigned long long ull;

// ---------------- scratch (device globals; no allocation) ----------------
__device__ float g_h[NTOT * DDIM];
__device__ float g_y[NTOT * DDIM];
__device__ float g_z[NTOT * DDIM];
__device__ float g_als[NTOT];
__device__ float g_ald[NTOT];
__device__ float g_zsum[NAB];
__device__ float g_sum[2 * DDIM];
__device__ float g_ssq[2 * DDIM];
__device__ float g_sumAB[2 * DDIM];
__device__ float g_ssqAB[2 * DDIM];

__device__ __forceinline__ float lrelu(float e) { return e > 0.f ? e : 0.2f * e; }

// ---- packed f32x2 helpers (Blackwell FFMA2) ----
__device__ __forceinline__ ull dup2(float s) {
    ull d; unsigned u = __float_as_uint(s);
    asm("mov.b64 %0, {%1, %1};" : "=l"(d) : "r"(u));
    return d;
}
__device__ __forceinline__ void ffma2(ull& acc, ull a, ull b) {
    asm("fma.rn.f32x2 %0, %1, %2, %0;" : "+l"(acc) : "l"(a), "l"(b));
}
__device__ __forceinline__ void unpk(float& lo, float& hi, ull v) {
    unsigned a, b;
    asm("mov.b64 {%0, %1}, %2;" : "=r"(a), "=r"(b) : "l"(v));
    lo = __uint_as_float(a); hi = __uint_as_float(b);
}

// ---- bf16 HMMA (sm_80 PTX; runs on sm_103 fallback HMMA tensor path) ----
__device__ __forceinline__ void mma_bf16(float* d, const unsigned* a,
                                         unsigned b0, unsigned b1) {
    asm volatile(
        "mma.sync.aligned.m16n8k16.row.col.f32.bf16.bf16.f32 "
        "{%0,%1,%2,%3}, {%4,%5,%6,%7}, {%8,%9}, {%0,%1,%2,%3};\n"
        : "+f"(d[0]), "+f"(d[1]), "+f"(d[2]), "+f"(d[3])
        : "r"(a[0]), "r"(a[1]), "r"(a[2]), "r"(a[3]), "r"(b0), "r"(b1));
}
__device__ __forceinline__ unsigned pack_bf16(float a, float b) {
    union { __nv_bfloat162 v; unsigned u; } p;
    p.v = __halves2bfloat162(__float2bfloat16(a), __float2bfloat16(b));
    return p.u;
}

// ---------------- GEMM via split-bf16 HMMA: H = X @ W, + als/ald dots ----------------
// 130 blocks x 256 thr (8 warps), 128 rows x 128 cols per block.
// X,W split into bf16 hi/lo; 3 passes (hh, hl, lh) accumulated in fp32.
#define RSTR 272            // smem row stride bytes (136 bf16) -> conflict-free frags
#define SX_H 0
#define SX_L 34816
#define SW_H 69632
#define SW_L 104448
#define S_AS 139264
#define S_AD 139776
#define S_LS 140288
#define S_LD 140800
#define SMEM_GEMM 141312

__global__ void __launch_bounds__(256, 1)
k_gemm(const float* __restrict__ X0, const float* __restrict__ X1,
       const float* __restrict__ W,
       const float* __restrict__ asrc, const float* __restrict__ adst,
       float* __restrict__ H, float* __restrict__ ALS, float* __restrict__ ALD,
       float* __restrict__ yz) {
    extern __shared__ char smem[];
    float* as_sh = (float*)(smem + S_AS);
    float* ad_sh = (float*)(smem + S_AD);
    float* sALS  = (float*)(smem + S_LS);
    float* sALD  = (float*)(smem + S_LD);
    const int t = threadIdx.x;
    const int row0 = blockIdx.x * 128;

    // zero AB region of aggregation target + zsum (blocks 0,1)
    if (row0 < NAB) {
        float4* z4 = reinterpret_cast<float4*>(yz) + row0 * 32;
#pragma unroll
        for (int i = 0; i < 16; i++) z4[t + 256 * i] = make_float4(0.f, 0.f, 0.f, 0.f);
        if (blockIdx.x == 0) g_zsum[t] = 0.f;
    }

    if (t < 128) { as_sh[t] = asrc[t]; ad_sh[t] = adst[t]; sALS[t] = 0.f; sALD[t] = 0.f; }

    // ---- split W into bf16 hi/lo, transposed to [n][k] ----
    for (int i = t; i < 8192; i += 256) {
        int n = i & 127, kk = i >> 7;                 // k elements 2kk, 2kk+1
        float w0 = W[(size_t)(2 * kk) * 128 + n];
        float w1 = W[(size_t)(2 * kk + 1) * 128 + n];
        __nv_bfloat16 h0 = __float2bfloat16(w0), h1 = __float2bfloat16(w1);
        float l0 = w0 - __bfloat162float(h0), l1 = w1 - __bfloat162float(h1);
        union { __nv_bfloat162 v; unsigned u; } ph, pl;
        ph.v = __halves2bfloat162(h0, h1);
        pl.v = __halves2bfloat162(__float2bfloat16(l0), __float2bfloat16(l1));
        *(unsigned*)(smem + SW_H + n * RSTR + 4 * kk) = ph.u;
        *(unsigned*)(smem + SW_L + n * RSTR + 4 * kk) = pl.u;
    }

    // ---- split X tile into bf16 hi/lo, row-major [r][k] ----
    const float* X = (row0 < NAB) ? (X0 + (size_t)row0 * DDIM)
                                  : (X1 + (size_t)(row0 - NAB) * DDIM);
    for (int i = t; i < 8192; i += 256) {
        int r = i >> 6, kk = i & 63;
        float2 x = *(const float2*)(X + (size_t)r * 128 + 2 * kk);
        __nv_bfloat16 h0 = __float2bfloat16(x.x), h1 = __float2bfloat16(x.y);
        float l0 = x.x - __bfloat162float(h0), l1 = x.y - __bfloat162float(h1);
        union { __nv_bfloat162 v; unsigned u; } ph, pl;
        ph.v = __halves2bfloat162(h0, h1);
        pl.v = __halves2bfloat162(__float2bfloat16(l0), __float2bfloat16(l1));
        *(unsigned*)(smem + SX_H + r * RSTR + 4 * kk) = ph.u;
        *(unsigned*)(smem + SX_L + r * RSTR + 4 * kk) = pl.u;
    }
    __syncthreads();

    const int wid = t >> 5, lane = t & 31;
    const int g = lane >> 2, c = lane & 3;
    const int mrow0 = (wid >> 1) * 32;      // 4 m-groups of 32 rows
    const int ncol0 = (wid & 1) * 64;       // 2 n-groups of 64 cols

    float acc[2][8][4];
#pragma unroll
    for (int mt = 0; mt < 2; mt++)
#pragma unroll
        for (int nt = 0; nt < 8; nt++)
#pragma unroll
            for (int q = 0; q < 4; q++) acc[mt][nt][q] = 0.f;

    const int xoffs[3] = { SX_H, SX_H, SX_L };
    const int woffs[3] = { SW_H, SW_L, SW_H };
    const int lbase = g * RSTR + 4 * c;

    for (int p = 0; p < 3; p++) {
        const char* Xb = smem + xoffs[p] + mrow0 * RSTR + lbase;
        const char* Bb = smem + woffs[p] + ncol0 * RSTR + lbase;
#pragma unroll 2
        for (int k0 = 0; k0 < 8; k0++) {
            unsigned a[2][4];
#pragma unroll
            for (int mt = 0; mt < 2; mt++) {
                const char* A = Xb + mt * (16 * RSTR) + k0 * 32;
                a[mt][0] = *(const unsigned*)(A);
                a[mt][1] = *(const unsigned*)(A + 8 * RSTR);
                a[mt][2] = *(const unsigned*)(A + 16);
                a[mt][3] = *(const unsigned*)(A + 8 * RSTR + 16);
            }
#pragma unroll
            for (int nt = 0; nt < 8; nt++) {
                const char* B = Bb + nt * (8 * RSTR) + k0 * 32;
                unsigned b0 = *(const unsigned*)(B);
                unsigned b1 = *(const unsigned*)(B + 16);
                mma_bf16(acc[0][nt], a[0], b0, b1);
                mma_bf16(acc[1][nt], a[1], b0, b1);
            }
        }
    }

    // ---- epilogue: H stores + per-row als/ald dots ----
#pragma unroll
    for (int mt = 0; mt < 2; mt++) {
        const int rA = mrow0 + mt * 16 + g;
        const int rB = rA + 8;
        float psA = 0.f, pdA = 0.f, psB = 0.f, pdB = 0.f;
#pragma unroll
        for (int nt = 0; nt < 8; nt++) {
            const int C = ncol0 + nt * 8 + 2 * c;
            float d0 = acc[mt][nt][0], d1 = acc[mt][nt][1];
            float d2 = acc[mt][nt][2], d3 = acc[mt][nt][3];
            *(float2*)(H + (size_t)(row0 + rA) * DDIM + C) = make_float2(d0, d1);
            *(float2*)(H + (size_t)(row0 + rB) * DDIM + C) = make_float2(d2, d3);
            float a0 = as_sh[C], a1 = as_sh[C + 1];
            float e0 = ad_sh[C], e1 = ad_sh[C + 1];
            psA += d0 * a0 + d1 * a1;  pdA += d0 * e0 + d1 * e1;
            psB += d2 * a0 + d3 * a1;  pdB += d2 * e0 + d3 * e1;
        }
#pragma unroll
        for (int off = 1; off <= 2; off <<= 1) {
            psA += __shfl_xor_sync(0xffffffffu, psA, off);
            pdA += __shfl_xor_sync(0xffffffffu, pdA, off);
            psB += __shfl_xor_sync(0xffffffffu, psB, off);
            pdB += __shfl_xor_sync(0xffffffffu, pdB, off);
        }
        if (c == 0) {
            atomicAdd(&sALS[rA], psA); atomicAdd(&sALD[rA], pdA);
            atomicAdd(&sALS[rB], psB); atomicAdd(&sALD[rB], pdB);
        }
    }
    __syncthreads();
    if (t < 128) {
        ALS[row0 + t] = sALS[t];
        ALD[row0 + t] = sALD[t];
    }
}

// ---------------- fused aggregation + softmax (no max-shift) ----------------
__global__ void __launch_bounds__(256, 3)
k_agg(const float* __restrict__ h, const float* __restrict__ als,
      const float* __restrict__ ald, const float* __restrict__ bias,
      float* __restrict__ y, int do_relu) {
    __shared__ __align__(16) float sbig[8192];
    __shared__ float4 swT[8][32];
    __shared__ float ssmall[16];
    const int t = threadIdx.x;

    if (blockIdx.x < 256) {
        // -------- AB dsts --------
        const int blk = blockIdx.x;
        const int b = blk >> 5, q = (blk >> 2) & 7, dq = blk & 3;
        const int base = NAB + b * GSZ + q * 256;
        const int d0 = b * 32 + dq * 8;
        float* ald_sh = ssmall;
        float* szs = ssmall + 8;
        if (t < 8) { ald_sh[t] = ald[d0 + t]; szs[t] = 0.f; }
        __syncthreads();
        {
            const int dme = t & 7;
            const float aldme = ald_sh[dme];
            float zloc = 0.f;
#pragma unroll
            for (int i = 0; i < 8; i++) {
                int idx = t + 256 * i;
                int j = idx >> 3;
                float e = __expf(lrelu(als[base + j] + aldme));
                sbig[idx] = e;
                zloc += e;
            }
            atomicAdd(&szs[dme], zloc);
        }
        __syncthreads();
        if (t < 8) atomicAdd(&g_zsum[d0 + t], szs[t]);

        const int c4 = t & 31, rs = t >> 5;
        ull acc2[4][4];
#pragma unroll
        for (int dp = 0; dp < 4; dp++)
#pragma unroll
            for (int c = 0; c < 4; c++) acc2[dp][c] = 0ull;

        const float4* h4 = reinterpret_cast<const float4*>(h) + (size_t)base * 32 + c4;
        const ull* w8 = reinterpret_cast<const ull*>(sbig);
#pragma unroll 8
        for (int jj = 0; jj < 32; jj++) {
            const int j = rs * 32 + jj;
            float4 hv = h4[(size_t)j * 32];
            ull hd0 = dup2(hv.x), hd1 = dup2(hv.y), hd2 = dup2(hv.z), hd3 = dup2(hv.w);
#pragma unroll
            for (int dp = 0; dp < 4; dp++) {
                ull a = w8[j * 4 + dp];
                ffma2(acc2[dp][0], a, hd0); ffma2(acc2[dp][1], a, hd1);
                ffma2(acc2[dp][2], a, hd2); ffma2(acc2[dp][3], a, hd3);
            }
        }
        __syncthreads();
        float4* st4 = reinterpret_cast<float4*>(sbig) + rs * 256;
#pragma unroll
        for (int dp = 0; dp < 4; dp++) {
            float4 ve, vo;
            unpk(ve.x, vo.x, acc2[dp][0]);
            unpk(ve.y, vo.y, acc2[dp][1]);
            unpk(ve.z, vo.z, acc2[dp][2]);
            unpk(ve.w, vo.w, acc2[dp][3]);
            st4[(2 * dp) * 32 + c4] = ve;
            st4[(2 * dp + 1) * 32 + c4] = vo;
        }
        __syncthreads();
        float s0 = 0.f, s1 = 0.f, s2 = 0.f, s3 = 0.f;
#pragma unroll
        for (int rr = 0; rr < 8; rr++) {
            float4 v = reinterpret_cast<const float4*>(sbig)[rr * 256 + t];
            s0 += v.x; s1 += v.y; s2 += v.z; s3 += v.w;
        }
        const int d = t >> 5, c = (t & 31) * 4;
        float* yo = y + (size_t)(d0 + d) * DDIM + c;
        atomicAdd(yo + 0, s0); atomicAdd(yo + 1, s1);
        atomicAdd(yo + 2, s2); atomicAdd(yo + 3, s3);
    } else {
        // -------- AG dsts --------
        const int ablk = blockIdx.x - 256;
        const int b = ablk >> 6, chunk = ablk & 63;
        {
            const float4* hsrc = reinterpret_cast<const float4*>(h + (size_t)b * 32 * DDIM);
            float4* hd = reinterpret_cast<float4*>(sbig);
#pragma unroll
            for (int i = 0; i < 4; i++) hd[t + 256 * i] = hsrc[t + 256 * i];
        }
        __shared__ float als_sh[32];
        if (t < 32) als_sh[t] = als[b * 32 + t];
        __syncthreads();
        const int w = t >> 5, l = t & 31;
        const int j0 = NAB + b * GSZ + chunk * 32 + w * 4;

        float wv[4], inv[4], wself[4];
#pragma unroll
        for (int d = 0; d < 4; d++) {
            float aldv = ald[j0 + d];
            wv[d] = __expf(lrelu(als_sh[l] + aldv));
            wself[d] = __expf(lrelu(als[j0 + d] + aldv));
            float s = wv[d];
#pragma unroll
            for (int off = 16; off; off >>= 1) s += __shfl_xor_sync(0xffffffffu, s, off);
            inv[d] = 1.f / (s + wself[d] + 1e-16f);
        }
        swT[w][l] = make_float4(wv[0], wv[1], wv[2], wv[3]);
        __syncwarp();

        ull acc01[4], acc23[4];
#pragma unroll
        for (int c = 0; c < 4; c++) { acc01[c] = 0ull; acc23[c] = 0ull; }

        const float4* hab4 = reinterpret_cast<const float4*>(sbig);
        const ulonglong2* swu = reinterpret_cast<const ulonglong2*>(&swT[w][0]);
#pragma unroll 8
        for (int l2 = 0; l2 < 32; l2++) {
            ulonglong2 wq = swu[l2];
            float4 hv = hab4[l2 * 32 + l];
            ull hd;
            hd = dup2(hv.x); ffma2(acc01[0], wq.x, hd); ffma2(acc23[0], wq.y, hd);
            hd = dup2(hv.y); ffma2(acc01[1], wq.x, hd); ffma2(acc23[1], wq.y, hd);
            hd = dup2(hv.z); ffma2(acc01[2], wq.x, hd); ffma2(acc23[2], wq.y, hd);
            hd = dup2(hv.w); ffma2(acc01[3], wq.x, hd); ffma2(acc23[3], wq.y, hd);
        }
        float sd[4][4];
#pragma unroll
        for (int c = 0; c < 4; c++) {
            unpk(sd[0][c], sd[1][c], acc01[c]);
            unpk(sd[2][c], sd[3][c], acc23[c]);
        }
        float4 b4 = reinterpret_cast<const float4*>(bias)[l];
#pragma unroll
        for (int d = 0; d < 4; d++) {
            float4 hs = reinterpret_cast<const float4*>(h + (size_t)(j0 + d) * DDIM)[l];
            float4 r;
            r.x = (sd[d][0] + wself[d] * hs.x) * inv[d] + b4.x;
            r.y = (sd[d][1] + wself[d] * hs.y) * inv[d] + b4.y;
            r.z = (sd[d][2] + wself[d] * hs.z) * inv[d] + b4.z;
            r.w = (sd[d][3] + wself[d] * hs.w) * inv[d] + b4.w;
            if (do_relu) {
                r.x = fmaxf(r.x, 0.f); r.y = fmaxf(r.y, 0.f);
                r.z = fmaxf(r.z, 0.f); r.w = fmaxf(r.w, 0.f);
            }
            reinterpret_cast<float4*>(y + (size_t)(j0 + d) * DDIM)[l] = r;
        }
    }
}

// ---------------- finalize AB rows + zero BN accumulators ----------------
__global__ void k_fin_ab(float* __restrict__ y, const float* __restrict__ h,
                         const float* __restrict__ als, const float* __restrict__ ald,
                         const float* __restrict__ bias, int do_relu) {
    int idx = blockIdx.x * 256 + threadIdx.x;
    if (blockIdx.x == 0) {
        g_sum[threadIdx.x] = 0.f;   g_ssq[threadIdx.x] = 0.f;
        g_sumAB[threadIdx.x] = 0.f; g_ssqAB[threadIdx.x] = 0.f;
    }
    int i = idx >> 7, c = idx & 127;
    float es = __expf(lrelu(als[i] + ald[i]));
    float v = (y[idx] + es * h[idx]) / (g_zsum[i] + es + 1e-16f) + bias[c];
    if (do_relu) v = fmaxf(v, 0.f);
    y[idx] = v;
}

// ---------------- BN stats: AB (blocks 0..3) + AG (blocks 4..259), atomics ----------------
__global__ void k_stats(const float* __restrict__ ab, const float* __restrict__ ag) {
    int c = threadIdx.x;
    float s = 0.f, ss = 0.f;
    if (blockIdx.x < 4) {
        int r0 = blockIdx.x * 64;
        const float* src = (c < 128) ? (g_z + (size_t)r0 * DDIM + c)
                                     : (ab + (size_t)r0 * DDIM + c - 128);
        for (int r = 0; r < 64; r++) {
            float v = src[(size_t)r * DDIM];
            s += v; ss += v * v;
        }
        atomicAdd(&g_sumAB[c], s);
        atomicAdd(&g_ssqAB[c], ss);
    } else {
        int r0 = (blockIdx.x - 4) * 64;
        const float* src = (c < 128) ? (g_z + (size_t)(NAB + r0) * DDIM + c)
                                     : (ag + (size_t)r0 * DDIM + c - 128);
        for (int r = 0; r < 64; r++) {
            float v = src[(size_t)r * DDIM];
            s += v; ss += v * v;
        }
        atomicAdd(&g_sum[c], s);
        atomicAdd(&g_ssq[c], ss);
    }
}

__device__ __forceinline__ void bnss(float s, float q, float g, float b, float invn,
                                     float& sc, float& sh) {
    float mean = s * invn;
    float var = q * invn - mean * mean;
    sc = g * rsqrtf(var + 1e-5f);
    sh = b - mean * sc;
}

// ---------------- fused BN -> ReLU -> FC epilogue ----------------
__global__ void k_apply(float* __restrict__ out,
                        const float* __restrict__ ab, const float* __restrict__ ag,
                        const float* __restrict__ fcw, const float* __restrict__ fcb,
                        const float* __restrict__ agw, const float* __restrict__ agb,
                        const float* __restrict__ gab, const float* __restrict__ bab,
                        const float* __restrict__ gag, const float* __restrict__ bag) {
    const int row = blockIdx.x * 8 + (threadIdx.x >> 5);
    const int l = threadIdx.x & 31;
    float4 v1 = reinterpret_cast<const float4*>(g_z + (size_t)row * DDIM)[l];
    float4 v2 = (row < NAB)
        ? reinterpret_cast<const float4*>(ab + (size_t)row * DDIM)[l]
        : reinterpret_cast<const float4*>(ag + (size_t)(row - NAB) * DDIM)[l];

    const float* psum; const float* pssq; const float* pg; const float* pb;
    const float* w; float fb; float invn;
    if (row < NAB) {
        psum = g_sumAB; pssq = g_ssqAB; pg = gab; pb = bab;
        w = fcw; fb = fcb[0]; invn = 1.f / (float)NAB;
    } else {
        psum = g_sum; pssq = g_ssq; pg = gag; pb = bag;
        w = agw; fb = agb[0]; invn = 1.f / (float)NAGN;
    }
    float4 s1 = reinterpret_cast<const float4*>(psum)[l];
    float4 q1 = reinterpret_cast<const float4*>(pssq)[l];
    float4 s2 = reinterpret_cast<const float4*>(psum)[32 + l];
    float4 q2 = reinterpret_cast<const float4*>(pssq)[32 + l];
    float4 gA = reinterpret_cast<const float4*>(pg)[l];
    float4 bA = reinterpret_cast<const float4*>(pb)[l];
    float4 gB = reinterpret_cast<const float4*>(pg)[32 + l];
    float4 bB = reinterpret_cast<const float4*>(pb)[32 + l];
    float4 scA, shAv, scB, shB;
    bnss(s1.x, q1.x, gA.x, bA.x, invn, scA.x, shAv.x);
    bnss(s1.y, q1.y, gA.y, bA.y, invn, scA.y, shAv.y);
    bnss(s1.z, q1.z, gA.z, bA.z, invn, scA.z, shAv.z);
    bnss(s1.w, q1.w, gA.w, bA.w, invn, scA.w, shAv.w);
    bnss(s2.x, q2.x, gB.x, bB.x, invn, scB.x, shB.x);
    bnss(s2.y, q2.y, gB.y, bB.y, invn, scB.y, shB.y);
    bnss(s2.z, q2.z, gB.z, bB.z, invn, scB.z, shB.z);
    bnss(s2.w, q2.w, gB.w, bB.w, invn, scB.w, shB.w);

    float4 w1 = reinterpret_cast<const float4*>(w)[l];
    float4 w2 = reinterpret_cast<const float4*>(w)[32 + l];
    float sum = 0.f;
    sum += fmaxf(v1.x * scA.x + shAv.x, 0.f) * w1.x;
    sum += fmaxf(v1.y * scA.y + shAv.y, 0.f) * w1.y;
    sum += fmaxf(v1.z * scA.z + shAv.z, 0.f) * w1.z;
    sum += fmaxf(v1.w * scA.w + shAv.w, 0.f) * w1.w;
    sum += fmaxf(v2.x * scB.x + shB.x, 0.f) * w2.x;
    sum += fmaxf(v2.y * scB.y + shB.y, 0.f) * w2.y;
    sum += fmaxf(v2.z * scB.z + shB.z, 0.f) * w2.z;
    sum += fmaxf(v2.w * scB.w + shB.w, 0.f) * w2.w;
#pragma unroll
    for (int off = 16; off; off >>= 1) sum += __shfl_xor_sync(0xffffffffu, sum, off);
    if (l == 0) out[row] = sum + fb;
}

// ---------------- host ----------------
extern "C" void kernel_launch(void* const* d_in, const int* in_sizes, int n_in,
                              void* d_out, int out_size) {
    const float* ab  = (const float*)d_in[0];
    const float* ag  = (const float*)d_in[1];
    const float* W1  = (const float*)d_in[2];
    const float* as1 = (const float*)d_in[3];
    const float* ad1 = (const float*)d_in[4];
    const float* b1  = (const float*)d_in[5];
    const float* W2  = (const float*)d_in[6];
    const float* as2 = (const float*)d_in[7];
    const float* ad2 = (const float*)d_in[8];
    const float* b2  = (const float*)d_in[9];
    const float* gab = (const float*)d_in[10];
    const float* bab = (const float*)d_in[11];
    const float* gag = (const float*)d_in[12];
    const float* bag = (const float*)d_in[13];
    const float* fcw = (const float*)d_in[14];
    const float* fcb = (const float*)d_in[15];
    const float* agw = (const float*)d_in[16];
    const float* agb = (const float*)d_in[17];
    float* out = (float*)d_out;

    float *ph, *py, *pz, *pals, *pald;
    cudaGetSymbolAddress((void**)&ph, g_h);
    cudaGetSymbolAddress((void**)&py, g_y);
    cudaGetSymbolAddress((void**)&pz, g_z);
    cudaGetSymbolAddress((void**)&pals, g_als);
    cudaGetSymbolAddress((void**)&pald, g_ald);

    cudaFuncSetAttribute(k_gemm, cudaFuncAttributeMaxDynamicSharedMemorySize, SMEM_GEMM);

    // ---- layer 1 ----
    k_gemm<<<130, 256, SMEM_GEMM>>>(ab, ag, W1, as1, ad1, ph, pals, pald, py);
    k_agg<<<768, 256>>>(ph, pals, pald, b1, py, 1);
    k_fin_ab<<<128, 256>>>(py, ph, pals, pald, b1, 1);

    // ---- layer 2 ----
    k_gemm<<<130, 256, SMEM_GEMM>>>(py, py + NAB * DDIM, W2, as2, ad2, ph, pals, pald, pz);
    k_agg<<<768, 256>>>(ph, pals, pald, b2, pz, 0);
    k_fin_ab<<<128, 256>>>(pz, ph, pals, pald, b2, 0);

    // ---- BN + FC epilogue ----
    k_stats<<<260, 256>>>(ab, ag);
    k_apply<<<2080, 256>>>(out, ab, ag, fcw, fcb, agw, agb, gab, bab, gag, bag);
}

// round 10
// speedup vs baseline: 1.4466x; 1.0410x over previous
#include <cuda_runtime.h>
#include <cuda_bf16.h>

#define NAB 256
#define NAGN 16384
#define NTOT 16640
#define DDIM 128
#define GSZ 2048

typedef unsigned long long ull;

// ---------------- scratch (device globals; no allocation) ----------------
__device__ float g_h[NTOT * DDIM];
__device__ float g_y[NTOT * DDIM];
__device__ float g_z[NTOT * DDIM];
__device__ float g_als[NTOT];
__device__ float g_ald[NTOT];
__device__ float g_zsum[NAB];
__device__ float g_sum[2 * DDIM];
__device__ float g_ssq[2 * DDIM];
__device__ float g_sumAB[2 * DDIM];
__device__ float g_ssqAB[2 * DDIM];
__device__ float4 g_wimg[4][2176];   // [layer*2 + (hi/lo)] : 128 rows x 272B bf16 images

__device__ __forceinline__ float lrelu(float e) { return e > 0.f ? e : 0.2f * e; }

// ---- packed f32x2 helpers (Blackwell FFMA2) ----
__device__ __forceinline__ ull dup2(float s) {
    ull d; unsigned u = __float_as_uint(s);
    asm("mov.b64 %0, {%1, %1};" : "=l"(d) : "r"(u));
    return d;
}
__device__ __forceinline__ void ffma2(ull& acc, ull a, ull b) {
    asm("fma.rn.f32x2 %0, %1, %2, %0;" : "+l"(acc) : "l"(a), "l"(b));
}
__device__ __forceinline__ void unpk(float& lo, float& hi, ull v) {
    unsigned a, b;
    asm("mov.b64 {%0, %1}, %2;" : "=r"(a), "=r"(b) : "l"(v));
    lo = __uint_as_float(a); hi = __uint_as_float(b);
}

// ---- bf16 HMMA (sm_80 PTX; runs on sm_103 fallback HMMA tensor path) ----
__device__ __forceinline__ void mma_bf16(float* d, const unsigned* a,
                                         unsigned b0, unsigned b1) {
    asm volatile(
        "mma.sync.aligned.m16n8k16.row.col.f32.bf16.bf16.f32 "
        "{%0,%1,%2,%3}, {%4,%5,%6,%7}, {%8,%9}, {%0,%1,%2,%3};\n"
        : "+f"(d[0]), "+f"(d[1]), "+f"(d[2]), "+f"(d[3])
        : "r"(a[0]), "r"(a[1]), "r"(a[2]), "r"(a[3]), "r"(b0), "r"(b1));
}

#define RSTR 272            // smem/global image row stride bytes (136 bf16)

// ---------------- prep: split W1/W2 into bf16 hi/lo images [n][k], once ----------------
// 8 blocks: layer = bid>>2, k-pair quarter = bid&3.
__global__ void k_prep(const float* __restrict__ W1, const float* __restrict__ W2) {
    const int layer = blockIdx.x >> 2, q = blockIdx.x & 3;
    const float* W = layer ? W2 : W1;
    char* hi_img = (char*)g_wimg[layer * 2];
    char* lo_img = (char*)g_wimg[layer * 2 + 1];
    for (int i = threadIdx.x; i < 2048; i += 256) {
        int n = i & 127, kk = q * 16 + (i >> 7);      // k elements 2kk, 2kk+1
        float w0 = W[(size_t)(2 * kk) * 128 + n];
        float w1 = W[(size_t)(2 * kk + 1) * 128 + n];
        __nv_bfloat16 h0 = __float2bfloat16(w0), h1 = __float2bfloat16(w1);
        float l0 = w0 - __bfloat162float(h0), l1 = w1 - __bfloat162float(h1);
        union { __nv_bfloat162 v; unsigned u; } ph, pl;
        ph.v = __halves2bfloat162(h0, h1);
        pl.v = __halves2bfloat162(__float2bfloat16(l0), __float2bfloat16(l1));
        *(unsigned*)(hi_img + n * RSTR + 4 * kk) = ph.u;
        *(unsigned*)(lo_img + n * RSTR + 4 * kk) = pl.u;
    }
}

// ---------------- GEMM via split-bf16 HMMA: H = X @ W, + als/ald dots ----------------
// 260 blocks x 256 thr (8 warps), 64 rows x 128 cols per block, warp tile 32x32.
// X split in-kernel; W images copied preformatted. 103.5KB smem -> 2 CTAs/SM.
#define SX_H 0
#define SX_L 17408
#define SW_H 34816
#define SW_L 69632
#define S_AS 104448
#define S_AD 104960
#define S_LS 105472
#define S_LD 105728
#define SMEM_GEMM 105984

__global__ void __launch_bounds__(256, 2)
k_gemm(const float* __restrict__ X0, const float* __restrict__ X1,
       const float4* __restrict__ wh, const float4* __restrict__ wl,
       const float* __restrict__ asrc, const float* __restrict__ adst,
       float* __restrict__ H, float* __restrict__ ALS, float* __restrict__ ALD,
       float* __restrict__ yz) {
    extern __shared__ char smem[];
    float* as_sh = (float*)(smem + S_AS);
    float* ad_sh = (float*)(smem + S_AD);
    float* sALS  = (float*)(smem + S_LS);
    float* sALD  = (float*)(smem + S_LD);
    const int t = threadIdx.x;
    const int row0 = blockIdx.x * 64;

    // zero AB region of aggregation target + zsum (blocks 0..3)
    if (row0 < NAB) {
        float4* z4 = reinterpret_cast<float4*>(yz) + row0 * 32;
#pragma unroll
        for (int i = 0; i < 8; i++) z4[t + 256 * i] = make_float4(0.f, 0.f, 0.f, 0.f);
        if (blockIdx.x == 0) g_zsum[t] = 0.f;
    }

    if (t < 128) { as_sh[t] = asrc[t]; ad_sh[t] = adst[t]; }
    if (t < 64) { sALS[t] = 0.f; sALD[t] = 0.f; }

    // ---- copy preformatted W hi/lo images (GMEM -> SMEM, float4) ----
    {
        float4* dh = (float4*)(smem + SW_H);
        float4* dl = (float4*)(smem + SW_L);
#pragma unroll
        for (int i = 0; i < 8; i++) {
            dh[t + 256 * i] = wh[t + 256 * i];
            dl[t + 256 * i] = wl[t + 256 * i];
        }
        if (t < 128) {
            dh[t + 2048] = wh[t + 2048];
            dl[t + 2048] = wl[t + 2048];
        }
    }

    // ---- split X tile (64 rows) into bf16 hi/lo, row-major [r][k] ----
    const float* X = (row0 < NAB) ? (X0 + (size_t)row0 * DDIM)
                                  : (X1 + (size_t)(row0 - NAB) * DDIM);
#pragma unroll
    for (int i0 = 0; i0 < 16; i0++) {
        int i = t + 256 * i0;
        int r = i >> 6, kk = i & 63;
        float2 x = *(const float2*)(X + (size_t)r * 128 + 2 * kk);
        __nv_bfloat16 h0 = __float2bfloat16(x.x), h1 = __float2bfloat16(x.y);
        float l0 = x.x - __bfloat162float(h0), l1 = x.y - __bfloat162float(h1);
        union { __nv_bfloat162 v; unsigned u; } ph, pl;
        ph.v = __halves2bfloat162(h0, h1);
        pl.v = __halves2bfloat162(__float2bfloat16(l0), __float2bfloat16(l1));
        *(unsigned*)(smem + SX_H + r * RSTR + 4 * kk) = ph.u;
        *(unsigned*)(smem + SX_L + r * RSTR + 4 * kk) = pl.u;
    }
    __syncthreads();

    const int wid = t >> 5, lane = t & 31;
    const int g = lane >> 2, c = lane & 3;
    const int mrow0 = (wid >> 2) * 32;      // 2 m-groups of 32 rows
    const int ncol0 = (wid & 3) * 32;       // 4 n-groups of 32 cols

    float acc[2][4][4];
#pragma unroll
    for (int mt = 0; mt < 2; mt++)
#pragma unroll
        for (int nt = 0; nt < 4; nt++)
#pragma unroll
            for (int q = 0; q < 4; q++) acc[mt][nt][q] = 0.f;

    const int xoffs[3] = { SX_H, SX_H, SX_L };
    const int woffs[3] = { SW_H, SW_L, SW_H };
    const int lbase = g * RSTR + 4 * c;

    for (int p = 0; p < 3; p++) {
        const char* Xb = smem + xoffs[p] + mrow0 * RSTR + lbase;
        const char* Bb = smem + woffs[p] + ncol0 * RSTR + lbase;
#pragma unroll 2
        for (int k0 = 0; k0 < 8; k0++) {
            unsigned a[2][4];
#pragma unroll
            for (int mt = 0; mt < 2; mt++) {
                const char* A = Xb + mt * (16 * RSTR) + k0 * 32;
                a[mt][0] = *(const unsigned*)(A);
                a[mt][1] = *(const unsigned*)(A + 8 * RSTR);
                a[mt][2] = *(const unsigned*)(A + 16);
                a[mt][3] = *(const unsigned*)(A + 8 * RSTR + 16);
            }
#pragma unroll
            for (int nt = 0; nt < 4; nt++) {
                const char* B = Bb + nt * (8 * RSTR) + k0 * 32;
                unsigned b0 = *(const unsigned*)(B);
                unsigned b1 = *(const unsigned*)(B + 16);
                mma_bf16(acc[0][nt], a[0], b0, b1);
                mma_bf16(acc[1][nt], a[1], b0, b1);
            }
        }
    }

    // ---- epilogue: H stores + per-row als/ald dots ----
#pragma unroll
    for (int mt = 0; mt < 2; mt++) {
        const int rA = mrow0 + mt * 16 + g;
        const int rB = rA + 8;
        float psA = 0.f, pdA = 0.f, psB = 0.f, pdB = 0.f;
#pragma unroll
        for (int nt = 0; nt < 4; nt++) {
            const int C = ncol0 + nt * 8 + 2 * c;
            float d0 = acc[mt][nt][0], d1 = acc[mt][nt][1];
            float d2 = acc[mt][nt][2], d3 = acc[mt][nt][3];
            *(float2*)(H + (size_t)(row0 + rA) * DDIM + C) = make_float2(d0, d1);
            *(float2*)(H + (size_t)(row0 + rB) * DDIM + C) = make_float2(d2, d3);
            float a0 = as_sh[C], a1 = as_sh[C + 1];
            float e0 = ad_sh[C], e1 = ad_sh[C + 1];
            psA += d0 * a0 + d1 * a1;  pdA += d0 * e0 + d1 * e1;
            psB += d2 * a0 + d3 * a1;  pdB += d2 * e0 + d3 * e1;
        }
#pragma unroll
        for (int off = 1; off <= 2; off <<= 1) {
            psA += __shfl_xor_sync(0xffffffffu, psA, off);
            pdA += __shfl_xor_sync(0xffffffffu, pdA, off);
            psB += __shfl_xor_sync(0xffffffffu, psB, off);
            pdB += __shfl_xor_sync(0xffffffffu, pdB, off);
        }
        if (c == 0) {
            atomicAdd(&sALS[rA], psA); atomicAdd(&sALD[rA], pdA);
            atomicAdd(&sALS[rB], psB); atomicAdd(&sALD[rB], pdB);
        }
    }
    __syncthreads();
    if (t < 64) {
        ALS[row0 + t] = sALS[t];
        ALD[row0 + t] = sALD[t];
    }
}

// ---------------- fused aggregation + softmax (no max-shift) ----------------
__global__ void __launch_bounds__(256, 3)
k_agg(const float* __restrict__ h, const float* __restrict__ als,
      const float* __restrict__ ald, const float* __restrict__ bias,
      float* __restrict__ y, int do_relu) {
    __shared__ __align__(16) float sbig[8192];
    __shared__ float4 swT[8][32];
    __shared__ float ssmall[16];
    const int t = threadIdx.x;

    if (blockIdx.x < 256) {
        // -------- AB dsts --------
        const int blk = blockIdx.x;
        const int b = blk >> 5, q = (blk >> 2) & 7, dq = blk & 3;
        const int base = NAB + b * GSZ + q * 256;
        const int d0 = b * 32 + dq * 8;
        float* ald_sh = ssmall;
        float* szs = ssmall + 8;
        if (t < 8) { ald_sh[t] = ald[d0 + t]; szs[t] = 0.f; }
        __syncthreads();
        {
            const int dme = t & 7;
            const float aldme = ald_sh[dme];
            float zloc = 0.f;
#pragma unroll
            for (int i = 0; i < 8; i++) {
                int idx = t + 256 * i;
                int j = idx >> 3;
                float e = __expf(lrelu(als[base + j] + aldme));
                sbig[idx] = e;
                zloc += e;
            }
            atomicAdd(&szs[dme], zloc);
        }
        __syncthreads();
        if (t < 8) atomicAdd(&g_zsum[d0 + t], szs[t]);

        const int c4 = t & 31, rs = t >> 5;
        ull acc2[4][4];
#pragma unroll
        for (int dp = 0; dp < 4; dp++)
#pragma unroll
            for (int c = 0; c < 4; c++) acc2[dp][c] = 0ull;

        const float4* h4 = reinterpret_cast<const float4*>(h) + (size_t)base * 32 + c4;
        const ull* w8 = reinterpret_cast<const ull*>(sbig);
#pragma unroll 8
        for (int jj = 0; jj < 32; jj++) {
            const int j = rs * 32 + jj;
            float4 hv = h4[(size_t)j * 32];
            ull hd0 = dup2(hv.x), hd1 = dup2(hv.y), hd2 = dup2(hv.z), hd3 = dup2(hv.w);
#pragma unroll
            for (int dp = 0; dp < 4; dp++) {
                ull a = w8[j * 4 + dp];
                ffma2(acc2[dp][0], a, hd0); ffma2(acc2[dp][1], a, hd1);
                ffma2(acc2[dp][2], a, hd2); ffma2(acc2[dp][3], a, hd3);
            }
        }
        __syncthreads();
        float4* st4 = reinterpret_cast<float4*>(sbig) + rs * 256;
#pragma unroll
        for (int dp = 0; dp < 4; dp++) {
            float4 ve, vo;
            unpk(ve.x, vo.x, acc2[dp][0]);
            unpk(ve.y, vo.y, acc2[dp][1]);
            unpk(ve.z, vo.z, acc2[dp][2]);
            unpk(ve.w, vo.w, acc2[dp][3]);
            st4[(2 * dp) * 32 + c4] = ve;
            st4[(2 * dp + 1) * 32 + c4] = vo;
        }
        __syncthreads();
        float s0 = 0.f, s1 = 0.f, s2 = 0.f, s3 = 0.f;
#pragma unroll
        for (int rr = 0; rr < 8; rr++) {
            float4 v = reinterpret_cast<const float4*>(sbig)[rr * 256 + t];
            s0 += v.x; s1 += v.y; s2 += v.z; s3 += v.w;
        }
        const int d = t >> 5, c = (t & 31) * 4;
        float* yo = y + (size_t)(d0 + d) * DDIM + c;
        atomicAdd(yo + 0, s0); atomicAdd(yo + 1, s1);
        atomicAdd(yo + 2, s2); atomicAdd(yo + 3, s3);
    } else {
        // -------- AG dsts --------
        const int ablk = blockIdx.x - 256;
        const int b = ablk >> 6, chunk = ablk & 63;
        {
            const float4* hsrc = reinterpret_cast<const float4*>(h + (size_t)b * 32 * DDIM);
            float4* hd = reinterpret_cast<float4*>(sbig);
#pragma unroll
            for (int i = 0; i < 4; i++) hd[t + 256 * i] = hsrc[t + 256 * i];
        }
        __shared__ float als_sh[32];
        if (t < 32) als_sh[t] = als[b * 32 + t];
        __syncthreads();
        const int w = t >> 5, l = t & 31;
        const int j0 = NAB + b * GSZ + chunk * 32 + w * 4;

        float wv[4], inv[4], wself[4];
#pragma unroll
        for (int d = 0; d < 4; d++) {
            float aldv = ald[j0 + d];
            wv[d] = __expf(lrelu(als_sh[l] + aldv));
            wself[d] = __expf(lrelu(als[j0 + d] + aldv));
            float s = wv[d];
#pragma unroll
            for (int off = 16; off; off >>= 1) s += __shfl_xor_sync(0xffffffffu, s, off);
            inv[d] = 1.f / (s + wself[d] + 1e-16f);
        }
        swT[w][l] = make_float4(wv[0], wv[1], wv[2], wv[3]);
        __syncwarp();

        ull acc01[4], acc23[4];
#pragma unroll
        for (int c = 0; c < 4; c++) { acc01[c] = 0ull; acc23[c] = 0ull; }

        const float4* hab4 = reinterpret_cast<const float4*>(sbig);
        const ulonglong2* swu = reinterpret_cast<const ulonglong2*>(&swT[w][0]);
#pragma unroll 8
        for (int l2 = 0; l2 < 32; l2++) {
            ulonglong2 wq = swu[l2];
            float4 hv = hab4[l2 * 32 + l];
            ull hd;
            hd = dup2(hv.x); ffma2(acc01[0], wq.x, hd); ffma2(acc23[0], wq.y, hd);
            hd = dup2(hv.y); ffma2(acc01[1], wq.x, hd); ffma2(acc23[1], wq.y, hd);
            hd = dup2(hv.z); ffma2(acc01[2], wq.x, hd); ffma2(acc23[2], wq.y, hd);
            hd = dup2(hv.w); ffma2(acc01[3], wq.x, hd); ffma2(acc23[3], wq.y, hd);
        }
        float sd[4][4];
#pragma unroll
        for (int c = 0; c < 4; c++) {
            unpk(sd[0][c], sd[1][c], acc01[c]);
            unpk(sd[2][c], sd[3][c], acc23[c]);
        }
        float4 b4 = reinterpret_cast<const float4*>(bias)[l];
#pragma unroll
        for (int d = 0; d < 4; d++) {
            float4 hs = reinterpret_cast<const float4*>(h + (size_t)(j0 + d) * DDIM)[l];
            float4 r;
            r.x = (sd[d][0] + wself[d] * hs.x) * inv[d] + b4.x;
            r.y = (sd[d][1] + wself[d] * hs.y) * inv[d] + b4.y;
            r.z = (sd[d][2] + wself[d] * hs.z) * inv[d] + b4.z;
            r.w = (sd[d][3] + wself[d] * hs.w) * inv[d] + b4.w;
            if (do_relu) {
                r.x = fmaxf(r.x, 0.f); r.y = fmaxf(r.y, 0.f);
                r.z = fmaxf(r.z, 0.f); r.w = fmaxf(r.w, 0.f);
            }
            reinterpret_cast<float4*>(y + (size_t)(j0 + d) * DDIM)[l] = r;
        }
    }
}

// ---------------- finalize AB rows + zero BN accumulators ----------------
__global__ void k_fin_ab(float* __restrict__ y, const float* __restrict__ h,
                         const float* __restrict__ als, const float* __restrict__ ald,
                         const float* __restrict__ bias, int do_relu) {
    int idx = blockIdx.x * 256 + threadIdx.x;
    if (blockIdx.x == 0) {
        g_sum[threadIdx.x] = 0.f;   g_ssq[threadIdx.x] = 0.f;
        g_sumAB[threadIdx.x] = 0.f; g_ssqAB[threadIdx.x] = 0.f;
    }
    int i = idx >> 7, c = idx & 127;
    float es = __expf(lrelu(als[i] + ald[i]));
    float v = (y[idx] + es * h[idx]) / (g_zsum[i] + es + 1e-16f) + bias[c];
    if (do_relu) v = fmaxf(v, 0.f);
    y[idx] = v;
}

// ---------------- BN stats: AB (blocks 0..3) + AG (blocks 4..259), atomics ----------------
__global__ void k_stats(const float* __restrict__ ab, const float* __restrict__ ag) {
    int c = threadIdx.x;
    float s = 0.f, ss = 0.f;
    if (blockIdx.x < 4) {
        int r0 = blockIdx.x * 64;
        const float* src = (c < 128) ? (g_z + (size_t)r0 * DDIM + c)
                                     : (ab + (size_t)r0 * DDIM + c - 128);
        for (int r = 0; r < 64; r++) {
            float v = src[(size_t)r * DDIM];
            s += v; ss += v * v;
        }
        atomicAdd(&g_sumAB[c], s);
        atomicAdd(&g_ssqAB[c], ss);
    } else {
        int r0 = (blockIdx.x - 4) * 64;
        const float* src = (c < 128) ? (g_z + (size_t)(NAB + r0) * DDIM + c)
                                     : (ag + (size_t)r0 * DDIM + c - 128);
        for (int r = 0; r < 64; r++) {
            float v = src[(size_t)r * DDIM];
            s += v; ss += v * v;
        }
        atomicAdd(&g_sum[c], s);
        atomicAdd(&g_ssq[c], ss);
    }
}

__device__ __forceinline__ void bnss(float s, float q, float g, float b, float invn,
                                     float& sc, float& sh) {
    float mean = s * invn;
    float var = q * invn - mean * mean;
    sc = g * rsqrtf(var + 1e-5f);
    sh = b - mean * sc;
}

// ---------------- fused BN -> ReLU -> FC epilogue ----------------
__global__ void k_apply(float* __restrict__ out,
                        const float* __restrict__ ab, const float* __restrict__ ag,
                        const float* __restrict__ fcw, const float* __restrict__ fcb,
                        const float* __restrict__ agw, const float* __restrict__ agb,
                        const float* __restrict__ gab, const float* __restrict__ bab,
                        const float* __restrict__ gag, const float* __restrict__ bag) {
    const int row = blockIdx.x * 8 + (threadIdx.x >> 5);
    const int l = threadIdx.x & 31;
    float4 v1 = reinterpret_cast<const float4*>(g_z + (size_t)row * DDIM)[l];
    float4 v2 = (row < NAB)
        ? reinterpret_cast<const float4*>(ab + (size_t)row * DDIM)[l]
        : reinterpret_cast<const float4*>(ag + (size_t)(row - NAB) * DDIM)[l];

    const float* psum; const float* pssq; const float* pg; const float* pb;
    const float* w; float fb; float invn;
    if (row < NAB) {
        psum = g_sumAB; pssq = g_ssqAB; pg = gab; pb = bab;
        w = fcw; fb = fcb[0]; invn = 1.f / (float)NAB;
    } else {
        psum = g_sum; pssq = g_ssq; pg = gag; pb = bag;
        w = agw; fb = agb[0]; invn = 1.f / (float)NAGN;
    }
    float4 s1 = reinterpret_cast<const float4*>(psum)[l];
    float4 q1 = reinterpret_cast<const float4*>(pssq)[l];
    float4 s2 = reinterpret_cast<const float4*>(psum)[32 + l];
    float4 q2 = reinterpret_cast<const float4*>(pssq)[32 + l];
    float4 gA = reinterpret_cast<const float4*>(pg)[l];
    float4 bA = reinterpret_cast<const float4*>(pb)[l];
    float4 gB = reinterpret_cast<const float4*>(pg)[32 + l];
    float4 bB = reinterpret_cast<const float4*>(pb)[32 + l];
    float4 scA, shAv, scB, shB;
    bnss(s1.x, q1.x, gA.x, bA.x, invn, scA.x, shAv.x);
    bnss(s1.y, q1.y, gA.y, bA.y, invn, scA.y, shAv.y);
    bnss(s1.z, q1.z, gA.z, bA.z, invn, scA.z, shAv.z);
    bnss(s1.w, q1.w, gA.w, bA.w, invn, scA.w, shAv.w);
    bnss(s2.x, q2.x, gB.x, bB.x, invn, scB.x, shB.x);
    bnss(s2.y, q2.y, gB.y, bB.y, invn, scB.y, shB.y);
    bnss(s2.z, q2.z, gB.z, bB.z, invn, scB.z, shB.z);
    bnss(s2.w, q2.w, gB.w, bB.w, invn, scB.w, shB.w);

    float4 w1 = reinterpret_cast<const float4*>(w)[l];
    float4 w2 = reinterpret_cast<const float4*>(w)[32 + l];
    float sum = 0.f;
    sum += fmaxf(v1.x * scA.x + shAv.x, 0.f) * w1.x;
    sum += fmaxf(v1.y * scA.y + shAv.y, 0.f) * w1.y;
    sum += fmaxf(v1.z * scA.z + shAv.z, 0.f) * w1.z;
    sum += fmaxf(v1.w * scA.w + shAv.w, 0.f) * w1.w;
    sum += fmaxf(v2.x * scB.x + shB.x, 0.f) * w2.x;
    sum += fmaxf(v2.y * scB.y + shB.y, 0.f) * w2.y;
    sum += fmaxf(v2.z * scB.z + shB.z, 0.f) * w2.z;
    sum += fmaxf(v2.w * scB.w + shB.w, 0.f) * w2.w;
#pragma unroll
    for (int off = 16; off; off >>= 1) sum += __shfl_xor_sync(0xffffffffu, sum, off);
    if (l == 0) out[row] = sum + fb;
}

// ---------------- host ----------------
extern "C" void kernel_launch(void* const* d_in, const int* in_sizes, int n_in,
                              void* d_out, int out_size) {
    const float* ab  = (const float*)d_in[0];
    const float* ag  = (const float*)d_in[1];
    const float* W1  = (const float*)d_in[2];
    const float* as1 = (const float*)d_in[3];
    const float* ad1 = (const float*)d_in[4];
    const float* b1  = (const float*)d_in[5];
    const float* W2  = (const float*)d_in[6];
    const float* as2 = (const float*)d_in[7];
    const float* ad2 = (const float*)d_in[8];
    const float* b2  = (const float*)d_in[9];
    const float* gab = (const float*)d_in[10];
    const float* bab = (const float*)d_in[11];
    const float* gag = (const float*)d_in[12];
    const float* bag = (const float*)d_in[13];
    const float* fcw = (const float*)d_in[14];
    const float* fcb = (const float*)d_in[15];
    const float* agw = (const float*)d_in[16];
    const float* agb = (const float*)d_in[17];
    float* out = (float*)d_out;

    float *ph, *py, *pz, *pals, *pald;
    float4* pw;
    cudaGetSymbolAddress((void**)&ph, g_h);
    cudaGetSymbolAddress((void**)&py, g_y);
    cudaGetSymbolAddress((void**)&pz, g_z);
    cudaGetSymbolAddress((void**)&pals, g_als);
    cudaGetSymbolAddress((void**)&pald, g_ald);
    cudaGetSymbolAddress((void**)&pw, g_wimg);

    cudaFuncSetAttribute(k_gemm, cudaFuncAttributeMaxDynamicSharedMemorySize, SMEM_GEMM);

    k_prep<<<8, 256>>>(W1, W2);

    // ---- layer 1 ----
    k_gemm<<<260, 256, SMEM_GEMM>>>(ab, ag, pw, pw + 2176, as1, ad1, ph, pals, pald, py);
    k_agg<<<768, 256>>>(ph, pals, pald, b1, py, 1);
    k_fin_ab<<<128, 256>>>(py, ph, pals, pald, b1, 1);

    // ---- layer 2 ----
    k_gemm<<<260, 256, SMEM_GEMM>>>(py, py + NAB * DDIM, pw + 4352, pw + 6528,
                                    as2, ad2, ph, pals, pald, pz);
    k_agg<<<768, 256>>>(ph, pals, pald, b2, pz, 0);
    k_fin_ab<<<128, 256>>>(pz, ph, pals, pald, b2, 0);

    // ---- BN + FC epilogue ----
    k_stats<<<260, 256>>>(ab, ag);
    k_apply<<<2080, 256>>>(out, ab, ag, fcw, fcb, agw, agb, gab, bab, gag, bag);
}